// round 12
// baseline (speedup 1.0000x reference)
#include <cuda_runtime.h>
#include <cuda_bf16.h>
#include <math.h>
#include <stdint.h>

#define T_   4096
#define H_   2048
#define E_   32
#define KTOP 4
#define I_   1408
#define R_   128
#define SI_  2816
#define TK_  (T_*KTOP)

// ======================= scratch (device globals) =======================
__device__ __align__(16) int   g_cnt[E_];
__device__ __align__(16) int   g_off[E_+1];
__device__ __align__(16) int   g_tok2d[E_*T_];
__device__ __align__(16) float g_w2d[E_*T_];
__device__ __align__(16) int   g_tokslot[TK_];
__device__ __align__(16) float g_wslot[TK_];
__device__ __align__(16) int   g_slot_of[TK_];
__device__ __align__(16) int   g_tokc[T_];

// split bf16 hi/lo buffers (lo plane(s) after hi plane(s))
__device__ __align__(16) __nv_bfloat16 g_xs    [2u*T_*H_];
__device__ __align__(16) __nv_bfloat16 g_w_proj[2u*4*R_*H_];
__device__ __align__(16) __nv_bfloat16 g_w_Ug  [2u*E_*R_*R_];
__device__ __align__(16) __nv_bfloat16 g_w_Uu  [2u*E_*R_*R_];
__device__ __align__(16) __nv_bfloat16 g_w_Ud  [2u*E_*R_*R_];
__device__ __align__(16) __nv_bfloat16 g_w_Cg  [2u*E_*I_*R_];
__device__ __align__(16) __nv_bfloat16 g_w_Cu  [2u*E_*I_*R_];
__device__ __align__(16) __nv_bfloat16 g_w_Cd  [2u*E_*H_*R_];
__device__ __align__(16) __nv_bfloat16 g_w_Rd  [2u*R_*I_];
__device__ __align__(16) __nv_bfloat16 g_w_sU  [2u*2*R_*R_];
__device__ __align__(16) __nv_bfloat16 g_w_sCg [2u*SI_*R_];
__device__ __align__(16) __nv_bfloat16 g_w_sCu [2u*SI_*R_];
__device__ __align__(16) __nv_bfloat16 g_w_sRd [2u*R_*SI_];
__device__ __align__(16) __nv_bfloat16 g_w_sUd [2u*R_*R_];
__device__ __align__(16) __nv_bfloat16 g_w_sCd [2u*H_*R_];

__device__ __align__(16) __nv_bfloat16 g_proj_s[2u*4*T_*R_];
__device__ __align__(16) __nv_bfloat16 g_tg_s  [2u*TK_*R_];
__device__ __align__(16) __nv_bfloat16 g_tu_s  [2u*TK_*R_];
__device__ __align__(16) float         g_hf    [(size_t)TK_*I_];
__device__ __align__(16) __nv_bfloat16 g_h_s   [2u*(size_t)TK_*I_];
__device__ __align__(16) __nv_bfloat16 g_rd_s  [2u*TK_*R_];
__device__ __align__(16) __nv_bfloat16 g_td_s  [2u*TK_*R_];
__device__ __align__(16) __nv_bfloat16 g_st_s  [2u*2*T_*R_];
__device__ __align__(16) float         g_shf   [(size_t)T_*SI_];
__device__ __align__(16) __nv_bfloat16 g_sh_s  [2u*(size_t)T_*SI_];
__device__ __align__(16) float         g_skp   [8u*T_*R_];
__device__ __align__(16) __nv_bfloat16 g_srd_s [2u*T_*R_];
__device__ __align__(16) __nv_bfloat16 g_std_s [2u*T_*R_];
__device__ __align__(16) float         g_eout  [(size_t)TK_*H_];

// ======================= helpers =======================
__device__ __forceinline__ uint32_t smem_u32_of(const void* p) {
    uint32_t a;
    asm("{ .reg .u64 t; cvta.to.shared.u64 t, %1; cvt.u32.u64 %0, t; }" : "=r"(a) : "l"(p));
    return a;
}
__device__ __forceinline__ void cpa16(uint32_t dst, const void* src, bool v) {
    int sz = v ? 16 : 0;
    asm volatile("cp.async.cg.shared.global [%0], [%1], 16, %2;\n" :: "r"(dst), "l"(src), "r"(sz));
}
__device__ __forceinline__ void ldm4(uint32_t* r, uint32_t addr) {
    asm volatile("ldmatrix.sync.aligned.m8n8.x4.shared.b16 {%0,%1,%2,%3}, [%4];"
                 : "=r"(r[0]), "=r"(r[1]), "=r"(r[2]), "=r"(r[3]) : "r"(addr));
}
__device__ __forceinline__ void mma_bf16(float* d, const uint32_t* a, const uint32_t* b) {
    asm volatile(
        "mma.sync.aligned.m16n8k16.row.col.f32.bf16.bf16.f32 "
        "{%0,%1,%2,%3},{%4,%5,%6,%7},{%8,%9},{%0,%1,%2,%3};\n"
        : "+f"(d[0]), "+f"(d[1]), "+f"(d[2]), "+f"(d[3])
        : "r"(a[0]), "r"(a[1]), "r"(a[2]), "r"(a[3]), "r"(b[0]), "r"(b[1]));
}
__device__ __forceinline__ float epi_silu(float v) { return v / (1.f + expf(-v)); }

// ======================= mega-split =======================
#define NJOBS 19
struct SplitJobs {
    const float*   src[NJOBS];
    __nv_bfloat16* dh [NJOBS];
    __nv_bfloat16* dl [NJOBS];
    unsigned       n  [NJOBS];
    unsigned       sb [NJOBS+1];
};

__global__ void megasplit_kernel(SplitJobs J) {
    unsigned bx = blockIdx.x;
    int j = 0;
    #pragma unroll
    for (int k = 0; k < NJOBS; k++) if (bx >= J.sb[k+1]) j = k+1;
    unsigned local = bx - J.sb[j];
    size_t i = ((size_t)local*256 + threadIdx.x) * 4;
    if (i >= J.n[j]) return;
    const float* src = J.src[j];
    __nv_bfloat16* dh = J.dh[j];
    __nv_bfloat16* dl = J.dl[j];
    float4 v = *reinterpret_cast<const float4*>(src + i);
    __nv_bfloat16 h0 = __float2bfloat16(v.x), h1 = __float2bfloat16(v.y);
    __nv_bfloat16 h2 = __float2bfloat16(v.z), h3 = __float2bfloat16(v.w);
    __nv_bfloat16 l0 = __float2bfloat16(v.x - __bfloat162float(h0));
    __nv_bfloat16 l1 = __float2bfloat16(v.y - __bfloat162float(h1));
    __nv_bfloat16 l2 = __float2bfloat16(v.z - __bfloat162float(h2));
    __nv_bfloat16 l3 = __float2bfloat16(v.w - __bfloat162float(h3));
    *reinterpret_cast<__nv_bfloat162*>(dh + i)     = __halves2bfloat162(h0, h1);
    *reinterpret_cast<__nv_bfloat162*>(dh + i + 2) = __halves2bfloat162(h2, h3);
    *reinterpret_cast<__nv_bfloat162*>(dl + i)     = __halves2bfloat162(l0, l1);
    *reinterpret_cast<__nv_bfloat162*>(dl + i + 2) = __halves2bfloat162(l2, l3);
}

// ======================= routing =======================
__global__ void init_kernel() {
    int i = blockIdx.x*256 + threadIdx.x;
    if (i < E_) g_cnt[i] = 0;
    if (i < T_) g_tokc[i] = 0;
}
__global__ void gate_kernel(const float* __restrict__ x, const float* __restrict__ gw) {
    __shared__ float xs[H_];
    __shared__ float lg[E_];
    int t = blockIdx.x;
    const float* xr = x + (size_t)t*H_;
    for (int i = threadIdx.x; i < H_; i += 256) xs[i] = xr[i];
    __syncthreads();
    int warp = threadIdx.x >> 5, lane = threadIdx.x & 31;
    for (int e = warp; e < E_; e += 8) {
        const float* w = gw + (size_t)e*H_;
        float s = 0.f;
        for (int i = lane; i < H_; i += 32) s += xs[i]*w[i];
        #pragma unroll
        for (int o = 16; o; o >>= 1) s += __shfl_xor_sync(0xffffffffu, s, o);
        if (lane == 0) lg[e] = s;
    }
    __syncthreads();
    if (threadIdx.x == 0) {
        float mx = lg[0];
        for (int e = 1; e < E_; e++) mx = fmaxf(mx, lg[e]);
        float p[E_]; float sum = 0.f;
        for (int e = 0; e < E_; e++) { p[e] = expf(lg[e]-mx); sum += p[e]; }
        float inv = 1.f/sum;
        bool taken[E_];
        for (int e = 0; e < E_; e++) taken[e] = false;
        int idx[KTOP]; float w4[KTOP]; float ws = 0.f;
        for (int k = 0; k < KTOP; k++) {
            int best = 0; float bv = -1.f;
            for (int e = 0; e < E_; e++)
                if (!taken[e] && p[e] > bv) { bv = p[e]; best = e; }
            taken[best] = true; idx[k] = best; w4[k] = bv*inv; ws += w4[k];
        }
        float rn = 1.f/(ws + 1e-20f);
        for (int k = 0; k < KTOP; k++) {
            int e = idx[k];
            int pos = atomicAdd(&g_cnt[e], 1);
            g_tok2d[e*T_ + pos] = t;
            g_w2d [e*T_ + pos] = w4[k]*rn;
        }
    }
}
__global__ void scan_kernel() {
    if (threadIdx.x == 0 && blockIdx.x == 0) {
        int a = 0;
        for (int e = 0; e < E_; e++) { g_off[e] = a; a += g_cnt[e]; }
        g_off[E_] = a;
    }
}
__global__ void compact_kernel() {
    int e = blockIdx.y;
    int i = blockIdx.x*256 + threadIdx.x;
    if (i < g_cnt[e]) {
        int slot = g_off[e] + i;
        int tok = g_tok2d[e*T_ + i];
        g_tokslot[slot] = tok;
        g_wslot[slot]   = g_w2d[e*T_ + i];
        int c = atomicAdd(&g_tokc[tok], 1);
        g_slot_of[tok*KTOP + c] = slot;
    }
}

// ======================= bf16-split mma.sync GEMM =======================
// 128x128 CTA tile, 4 warps of 64x64 (2m x 2n) -> smem read-amplification A×2,B×2
// (was 8 warps 32x64: A×2,B×4). 3-term bf16 split. 128 threads, 2 CTAs/SM.
// EPI: 0 split-store  1 silu->fp32  2 (res*Mul)->split-store  3 rowscale->fp32
//      4 fp32         5 fp32 + gather-add 4 expert slots
// ZMODE: 0 expert  1 dense-multi  2 split-K  3 dense-multi x split-K2

#define ROWW  20
#define TILEW (128*ROWW)
#define GSMEM (8*TILEW*4)
#define NTHR  128

template<int EPI, int ZMODE>
__global__ __launch_bounds__(NTHR, 2)
void bgemm(const __nv_bfloat16* __restrict__ Ah, int lda, size_t aplane, size_t astride,
           const __nv_bfloat16* __restrict__ Wh, int ldw, size_t wplane, size_t wstride,
           float* __restrict__ Cf,
           __nv_bfloat16* __restrict__ Ch, size_t cplane,
           const float* __restrict__ Mul,
           int ldc, size_t cstride,
           int M, int N, int Kd,
           const int* __restrict__ off,
           const int* __restrict__ rowmap,
           const float* __restrict__ rowscale)
{
    int z = blockIdx.z;
    int rs = 0, re = M;
    int kbase = 0;
    int zc = z;
    const __nv_bfloat16* A0 = Ah;
    const __nv_bfloat16* W0 = Wh;
    if (ZMODE == 0) { rs = off[z]; re = off[z+1]; W0 = Wh + (size_t)z*wstride; }
    else if (ZMODE == 1) { A0 = Ah + (size_t)z*astride; W0 = Wh + (size_t)z*wstride; }
    else if (ZMODE == 2) { kbase = z*Kd; }
    else {
        int zn = (int)(gridDim.z >> 1);
        int plane = z >> 1, kh = z & 1;
        A0 = Ah + (size_t)plane*astride;
        W0 = Wh + (size_t)plane*wstride;
        kbase = kh*Kd;
        zc = kh*zn + plane;
    }

    int row0 = rs + blockIdx.x * 128;
    if (row0 >= re) return;
    int col0 = blockIdx.y * 128;

    extern __shared__ uint32_t smw[];
    uint32_t sb = smem_u32_of(smw);

    int tid = threadIdx.x;
    int wid = tid >> 5, lane = tid & 31;
    int g = lane >> 2, t = lane & 3;
    int wm = wid & 1;        // 2 warps in m (64 rows each)
    int wn = wid >> 1;       // 2 warps in n (64 cols each)

    int aRow = ((lane >> 3) & 1)*8 + (lane & 7);
    int aCol = (lane >> 4)*4;
    int bRow = (lane >> 4)*8 + (lane & 7);
    int bCol = ((lane >> 3) & 1)*4;

    float acc[4][8][4];
    #pragma unroll
    for (int i = 0; i < 4; i++)
        #pragma unroll
        for (int j = 0; j < 8; j++)
            #pragma unroll
            for (int c = 0; c < 4; c++) acc[i][j][c] = 0.f;

    int iters = Kd / 32;

    auto stage = [&](int s, int kb) {
        uint32_t base = sb + (uint32_t)s*4*TILEW*4;
        #pragma unroll
        for (int it = 0; it < 16; it++) {
            int id = tid + it*NTHR;
            int tile = id >> 9;
            int rem = id & 511;
            int row = rem >> 2;
            int seg = rem & 3;
            uint32_t dst = base + (uint32_t)(tile*TILEW + row*ROWW + seg*4)*4;
            int kpos = kbase + kb + seg*8;
            if (tile < 2) {
                int r = row0 + row;
                bool v = (r < re);
                int ar = 0;
                if (v) ar = (ZMODE == 0 && rowmap) ? rowmap[r] : r;
                const __nv_bfloat16* Ab = (tile == 0) ? A0 : (A0 + aplane);
                cpa16(dst, Ab + (size_t)ar*lda + kpos, v);
            } else {
                int n = col0 + row;
                const __nv_bfloat16* Wb = (tile == 2) ? W0 : (W0 + wplane);
                cpa16(dst, Wb + (size_t)n*ldw + kpos, true);
            }
        }
    };

    stage(0, 0);
    asm volatile("cp.async.commit_group;\n");

    for (int kt = 0; kt < iters; kt++) {
        if (kt + 1 < iters) {
            stage((kt+1) & 1, (kt+1)*32);
            asm volatile("cp.async.commit_group;\n");
            asm volatile("cp.async.wait_group 1;\n");
        } else {
            asm volatile("cp.async.wait_group 0;\n");
        }
        __syncthreads();
        uint32_t base = sb + (uint32_t)(kt & 1)*4*TILEW*4;

        #pragma unroll
        for (int kk = 0; kk < 16; kk += 8) {
            uint32_t aH[4][4], aL[4][4];
            #pragma unroll
            for (int mt = 0; mt < 4; mt++) {
                uint32_t ro = (uint32_t)((wm*64 + mt*16 + aRow)*ROWW + kk + aCol)*4;
                ldm4(aH[mt], base + 0*TILEW*4 + ro);
                ldm4(aL[mt], base + 1*TILEW*4 + ro);
            }
            #pragma unroll
            for (int half = 0; half < 2; half++) {
                uint32_t bH[2][4], bL[2][4];
                #pragma unroll
                for (int pp = 0; pp < 2; pp++) {
                    int p2 = half*2 + pp;
                    uint32_t ro = (uint32_t)((wn*64 + p2*16 + bRow)*ROWW + kk + bCol)*4;
                    ldm4(bH[pp], base + 2*TILEW*4 + ro);
                    ldm4(bL[pp], base + 3*TILEW*4 + ro);
                }
                #pragma unroll
                for (int mt = 0; mt < 4; mt++) {
                    #pragma unroll
                    for (int n4 = 0; n4 < 4; n4++) {
                        int nt = half*4 + n4;
                        int pp = n4 >> 1, w = (n4 & 1)*2;
                        mma_bf16(acc[mt][nt], aL[mt], &bH[pp][w]);
                        mma_bf16(acc[mt][nt], aH[mt], &bL[pp][w]);
                        mma_bf16(acc[mt][nt], aH[mt], &bH[pp][w]);
                    }
                }
            }
        }
        __syncthreads();
    }

    float* Cf_z = Cf;
    __nv_bfloat16* Ch_z = Ch;
    if (ZMODE == 1 || ZMODE == 2 || ZMODE == 3) {
        Cf_z = Cf + (size_t)zc*cstride;
        Ch_z = Ch + (size_t)zc*cstride;
    }
    #pragma unroll
    for (int mt = 0; mt < 4; mt++) {
        #pragma unroll
        for (int half = 0; half < 2; half++) {
            int r = row0 + wm*64 + mt*16 + g + half*8;
            if (r >= re) continue;
            float rsc = (EPI == 3) ? rowscale[r] : 1.f;
            int sl[KTOP];
            if (EPI == 5) {
                #pragma unroll
                for (int k = 0; k < KTOP; k++) sl[k] = g_slot_of[r*KTOP + k];
            }
            #pragma unroll
            for (int nt = 0; nt < 8; nt++) {
                int cix = col0 + wn*64 + nt*8 + 2*t;
                float v0 = acc[mt][nt][half*2 + 0];
                float v1 = acc[mt][nt][half*2 + 1];
                if (EPI == 1) { v0 = epi_silu(v0); v1 = epi_silu(v1); }
                if (EPI == 3) { v0 *= rsc; v1 *= rsc; }
                if (EPI == 2) {
                    float2 m = *reinterpret_cast<const float2*>(Mul + (size_t)r*ldc + cix);
                    v0 *= m.x; v1 *= m.y;
                }
                if (EPI == 5) {
                    #pragma unroll
                    for (int k = 0; k < KTOP; k++) {
                        float2 e2 = *reinterpret_cast<const float2*>(g_eout + (size_t)sl[k]*H_ + cix);
                        v0 += e2.x; v1 += e2.y;
                    }
                }
                if (EPI == 0 || EPI == 2) {
                    __nv_bfloat16 h0 = __float2bfloat16(v0);
                    __nv_bfloat16 h1 = __float2bfloat16(v1);
                    __nv_bfloat16 l0 = __float2bfloat16(v0 - __bfloat162float(h0));
                    __nv_bfloat16 l1 = __float2bfloat16(v1 - __bfloat162float(h1));
                    __nv_bfloat16* p = Ch_z + (size_t)r*ldc + cix;
                    *reinterpret_cast<__nv_bfloat162*>(p)          = __halves2bfloat162(h0, h1);
                    *reinterpret_cast<__nv_bfloat162*>(p + cplane) = __halves2bfloat162(l0, l1);
                } else {
                    float2 vv; vv.x = v0; vv.y = v1;
                    *reinterpret_cast<float2*>(Cf_z + (size_t)r*ldc + cix) = vv;
                }
            }
        }
    }
}

// ======================= N-plane split-K reduce -> split bf16 =======================
__global__ void reduceN_split_kernel(const float* __restrict__ in, size_t pstride, int np,
                                     __nv_bfloat16* __restrict__ dh, __nv_bfloat16* __restrict__ dl,
                                     int n) {
    int i = (blockIdx.x*256 + threadIdx.x) * 2;
    if (i >= n) return;
    float v0 = in[i], v1 = in[i+1];
    for (int p = 1; p < np; p++) {
        v0 += in[(size_t)p*pstride + i];
        v1 += in[(size_t)p*pstride + i + 1];
    }
    __nv_bfloat16 h0 = __float2bfloat16(v0), h1 = __float2bfloat16(v1);
    __nv_bfloat16 l0 = __float2bfloat16(v0 - __bfloat162float(h0));
    __nv_bfloat16 l1 = __float2bfloat16(v1 - __bfloat162float(h1));
    *reinterpret_cast<__nv_bfloat162*>(dh + i) = __halves2bfloat162(h0, h1);
    *reinterpret_cast<__nv_bfloat162*>(dl + i) = __halves2bfloat162(l0, l1);
}

// ======================= host side =======================
template<typename Tp>
static Tp* sym(const void* s) {
    void* p = nullptr;
    cudaGetSymbolAddress(&p, s);
    return (Tp*)p;
}

extern "C" void kernel_launch(void* const* d_in, const int* in_sizes, int n_in,
                              void* d_out, int out_size)
{
    const float* x      = (const float*)d_in[0];
    const float* gate_w = (const float*)d_in[1];
    const float* Rg     = (const float*)d_in[2];
    const float* Ru     = (const float*)d_in[3];
    const float* Rd     = (const float*)d_in[4];
    const float* Ug     = (const float*)d_in[5];
    const float* Cg     = (const float*)d_in[6];
    const float* Uu     = (const float*)d_in[7];
    const float* Cu     = (const float*)d_in[8];
    const float* Ud     = (const float*)d_in[9];
    const float* Cd     = (const float*)d_in[10];
    const float* s_Rg   = (const float*)d_in[11];
    const float* s_Ug   = (const float*)d_in[12];
    const float* s_Cg   = (const float*)d_in[13];
    const float* s_Ru   = (const float*)d_in[14];
    const float* s_Uu   = (const float*)d_in[15];
    const float* s_Cu   = (const float*)d_in[16];
    const float* s_Rd   = (const float*)d_in[17];
    const float* s_Ud   = (const float*)d_in[18];
    const float* s_Cd   = (const float*)d_in[19];
    float* out = (float*)d_out;

    __nv_bfloat16* p_xs    = sym<__nv_bfloat16>(g_xs);
    __nv_bfloat16* p_wproj = sym<__nv_bfloat16>(g_w_proj);
    __nv_bfloat16* p_wUg   = sym<__nv_bfloat16>(g_w_Ug);
    __nv_bfloat16* p_wUu   = sym<__nv_bfloat16>(g_w_Uu);
    __nv_bfloat16* p_wUd   = sym<__nv_bfloat16>(g_w_Ud);
    __nv_bfloat16* p_wCg   = sym<__nv_bfloat16>(g_w_Cg);
    __nv_bfloat16* p_wCu   = sym<__nv_bfloat16>(g_w_Cu);
    __nv_bfloat16* p_wCd   = sym<__nv_bfloat16>(g_w_Cd);
    __nv_bfloat16* p_wRd   = sym<__nv_bfloat16>(g_w_Rd);
    __nv_bfloat16* p_wsU   = sym<__nv_bfloat16>(g_w_sU);
    __nv_bfloat16* p_wsCg  = sym<__nv_bfloat16>(g_w_sCg);
    __nv_bfloat16* p_wsCu  = sym<__nv_bfloat16>(g_w_sCu);
    __nv_bfloat16* p_wsRd  = sym<__nv_bfloat16>(g_w_sRd);
    __nv_bfloat16* p_wsUd  = sym<__nv_bfloat16>(g_w_sUd);
    __nv_bfloat16* p_wsCd  = sym<__nv_bfloat16>(g_w_sCd);

    __nv_bfloat16* p_projs = sym<__nv_bfloat16>(g_proj_s);
    __nv_bfloat16* p_tgs   = sym<__nv_bfloat16>(g_tg_s);
    __nv_bfloat16* p_tus   = sym<__nv_bfloat16>(g_tu_s);
    float*         p_hf    = sym<float>(g_hf);
    __nv_bfloat16* p_hs    = sym<__nv_bfloat16>(g_h_s);
    __nv_bfloat16* p_rds   = sym<__nv_bfloat16>(g_rd_s);
    __nv_bfloat16* p_tds   = sym<__nv_bfloat16>(g_td_s);
    __nv_bfloat16* p_sts   = sym<__nv_bfloat16>(g_st_s);
    float*         p_shf   = sym<float>(g_shf);
    __nv_bfloat16* p_shs   = sym<__nv_bfloat16>(g_sh_s);
    float*         p_skp   = sym<float>(g_skp);
    __nv_bfloat16* p_srds  = sym<__nv_bfloat16>(g_srd_s);
    __nv_bfloat16* p_stds  = sym<__nv_bfloat16>(g_std_s);
    float*         p_eout  = sym<float>(g_eout);
    int*   p_off = sym<int>(g_off);
    int*   p_map = sym<int>(g_tokslot);
    float* p_ws  = sym<float>(g_wslot);

    cudaFuncSetAttribute((const void*)bgemm<0,0>, cudaFuncAttributeMaxDynamicSharedMemorySize, GSMEM);
    cudaFuncSetAttribute((const void*)bgemm<0,1>, cudaFuncAttributeMaxDynamicSharedMemorySize, GSMEM);
    cudaFuncSetAttribute((const void*)bgemm<1,0>, cudaFuncAttributeMaxDynamicSharedMemorySize, GSMEM);
    cudaFuncSetAttribute((const void*)bgemm<1,1>, cudaFuncAttributeMaxDynamicSharedMemorySize, GSMEM);
    cudaFuncSetAttribute((const void*)bgemm<2,0>, cudaFuncAttributeMaxDynamicSharedMemorySize, GSMEM);
    cudaFuncSetAttribute((const void*)bgemm<2,1>, cudaFuncAttributeMaxDynamicSharedMemorySize, GSMEM);
    cudaFuncSetAttribute((const void*)bgemm<3,0>, cudaFuncAttributeMaxDynamicSharedMemorySize, GSMEM);
    cudaFuncSetAttribute((const void*)bgemm<4,2>, cudaFuncAttributeMaxDynamicSharedMemorySize, GSMEM);
    cudaFuncSetAttribute((const void*)bgemm<4,3>, cudaFuncAttributeMaxDynamicSharedMemorySize, GSMEM);
    cudaFuncSetAttribute((const void*)bgemm<5,1>, cudaFuncAttributeMaxDynamicSharedMemorySize, GSMEM);

    const size_t RH = (size_t)R_*H_, RR = (size_t)R_*R_;
    const size_t TR = (size_t)T_*R_, TKR = (size_t)TK_*R_, TKI = (size_t)TK_*I_, TSI = (size_t)T_*SI_;
    const size_t SIR = (size_t)SI_*R_;

    SplitJobs J;
    {
        const float* srcs[NJOBS] = { x, Rg, Ru, s_Rg, s_Ru, Ug, Uu, Ud, Cg, Cu, Cd, Rd,
                                     s_Ug, s_Uu, s_Cg, s_Cu, s_Rd, s_Ud, s_Cd };
        __nv_bfloat16* dhs[NJOBS] = {
            p_xs, p_wproj + 0*RH, p_wproj + 1*RH, p_wproj + 2*RH, p_wproj + 3*RH,
            p_wUg, p_wUu, p_wUd, p_wCg, p_wCu, p_wCd, p_wRd,
            p_wsU + 0*RR, p_wsU + 1*RR, p_wsCg, p_wsCu, p_wsRd, p_wsUd, p_wsCd };
        __nv_bfloat16* dls[NJOBS] = {
            p_xs + (size_t)T_*H_, p_wproj + 4*RH + 0*RH, p_wproj + 4*RH + 1*RH,
            p_wproj + 4*RH + 2*RH, p_wproj + 4*RH + 3*RH,
            p_wUg + (size_t)E_*RR, p_wUu + (size_t)E_*RR, p_wUd + (size_t)E_*RR,
            p_wCg + (size_t)E_*I_*R_, p_wCu + (size_t)E_*I_*R_, p_wCd + (size_t)E_*H_*R_,
            p_wRd + (size_t)R_*I_,
            p_wsU + 2*RR + 0*RR, p_wsU + 2*RR + 1*RR,
            p_wsCg + SIR, p_wsCu + SIR, p_wsRd + (size_t)R_*SI_,
            p_wsUd + RR, p_wsCd + (size_t)H_*R_ };
        size_t ns[NJOBS] = { (size_t)T_*H_, RH, RH, RH, RH,
                             (size_t)E_*RR, (size_t)E_*RR, (size_t)E_*RR,
                             (size_t)E_*I_*R_, (size_t)E_*I_*R_, (size_t)E_*H_*R_,
                             (size_t)R_*I_, RR, RR, SIR, SIR, (size_t)R_*SI_, RR, (size_t)H_*R_ };
        unsigned acc = 0;
        for (int j = 0; j < NJOBS; j++) {
            J.src[j] = srcs[j]; J.dh[j] = dhs[j]; J.dl[j] = dls[j];
            J.n[j] = (unsigned)ns[j];
            J.sb[j] = acc;
            acc += (unsigned)((ns[j] + 1023) / 1024);
        }
        J.sb[NJOBS] = acc;
    }

    megasplit_kernel<<<J.sb[NJOBS],256>>>(J);
    init_kernel<<<16,256>>>();
    gate_kernel<<<T_,256>>>(x, gate_w);
    // rank projections — ZMODE3 (4 planes x split-K2), 256 CTAs
    bgemm<4,3><<<dim3(32,1,8),NTHR,GSMEM>>>(p_xs, H_, (size_t)T_*H_, 0,
        p_wproj, H_, 4*RH, RH, p_skp, nullptr, 0, nullptr, R_, TR,
        T_, R_, H_/2, nullptr, nullptr, nullptr);
    scan_kernel<<<1,32>>>();
    compact_kernel<<<dim3(16,E_),256>>>();
    reduceN_split_kernel<<<(4*T_*R_/2+255)/256,256>>>(p_skp, 4*TR, 2, p_projs, p_projs + 4*TR, 4*T_*R_);

    // expert U (gather token rows)
    bgemm<0,0><<<dim3(32,1,E_),NTHR,GSMEM>>>(p_projs + 0*TR, R_, 4*TR, 0,
        p_wUg, R_, (size_t)E_*RR, RR, nullptr, p_tgs, TKR, nullptr, R_, 0,
        0, R_, R_, p_off, p_map, nullptr);
    bgemm<0,0><<<dim3(32,1,E_),NTHR,GSMEM>>>(p_projs + 1*TR, R_, 4*TR, 0,
        p_wUu, R_, (size_t)E_*RR, RR, nullptr, p_tus, TKR, nullptr, R_, 0,
        0, R_, R_, p_off, p_map, nullptr);
    // expert C-gate: silu -> fp32 hf
    bgemm<1,0><<<dim3(32,11,E_),NTHR,GSMEM>>>(p_tgs, R_, TKR, 0,
        p_wCg, R_, (size_t)E_*I_*R_, (size_t)I_*R_, p_hf, nullptr, 0, nullptr, I_, 0,
        0, I_, R_, p_off, nullptr, nullptr);
    // expert C-up: (res * hf) -> h split
    bgemm<2,0><<<dim3(32,11,E_),NTHR,GSMEM>>>(p_tus, R_, TKR, 0,
        p_wCu, R_, (size_t)E_*I_*R_, (size_t)I_*R_, nullptr, p_hs, TKI, p_hf, I_, 0,
        0, I_, R_, p_off, nullptr, nullptr);
    // Rd: split-K=2, 256 CTAs -> fp32 partials, reduce
    bgemm<4,2><<<dim3(128,1,2),NTHR,GSMEM>>>(p_hs, I_, TKI, 0,
        p_wRd, I_, (size_t)R_*I_, 0, p_skp, nullptr, 0, nullptr, R_, TKR,
        TK_, R_, I_/2, nullptr, nullptr, nullptr);
    reduceN_split_kernel<<<(TK_*R_/2+255)/256,256>>>(p_skp, TKR, 2, p_rds, p_rds + TKR, TK_*R_);
    // expert Ud
    bgemm<0,0><<<dim3(32,1,E_),NTHR,GSMEM>>>(p_rds, R_, TKR, 0,
        p_wUd, R_, (size_t)E_*RR, RR, nullptr, p_tds, TKR, nullptr, R_, 0,
        0, R_, R_, p_off, nullptr, nullptr);
    // expert Cd: rowscale -> eout fp32
    bgemm<3,0><<<dim3(32,16,E_),NTHR,GSMEM>>>(p_tds, R_, TKR, 0,
        p_wCd, R_, (size_t)E_*H_*R_, (size_t)H_*R_, p_eout, nullptr, 0, nullptr, H_, 0,
        0, H_, R_, p_off, nullptr, p_ws);
    // shared U (z over gate/up)
    bgemm<0,1><<<dim3(32,1,2),NTHR,GSMEM>>>(p_projs + 2*TR, R_, 4*TR, TR,
        p_wsU, R_, 2*RR, RR, nullptr, p_sts, 2*TR, nullptr, R_, TR,
        T_, R_, R_, nullptr, nullptr, nullptr);
    // shared C-gate: silu -> shf
    bgemm<1,1><<<dim3(32,22,1),NTHR,GSMEM>>>(p_sts + 0*TR, R_, 2*TR, 0,
        p_wsCg, R_, SIR, 0, p_shf, nullptr, 0, nullptr, SI_, 0,
        T_, SI_, R_, nullptr, nullptr, nullptr);
    // shared C-up: (res * shf) -> sh split
    bgemm<2,1><<<dim3(32,22,1),NTHR,GSMEM>>>(p_sts + 1*TR, R_, 2*TR, 0,
        p_wsCu, R_, SIR, 0, nullptr, p_shs, TSI, p_shf, SI_, 0,
        T_, SI_, R_, nullptr, nullptr, nullptr);
    // shared Rd: split-K=4 -> fp32 partials, reduce
    bgemm<4,2><<<dim3(32,1,4),NTHR,GSMEM>>>(p_shs, SI_, TSI, 0,
        p_wsRd, SI_, (size_t)R_*SI_, 0, p_skp, nullptr, 0, nullptr, R_, TR,
        T_, R_, SI_/4, nullptr, nullptr, nullptr);
    reduceN_split_kernel<<<(T_*R_/2+255)/256,256>>>(p_skp, TR, 4, p_srds, p_srds + TR, T_*R_);
    // shared Ud
    bgemm<0,1><<<dim3(32,1,1),NTHR,GSMEM>>>(p_srds, R_, TR, 0,
        p_wsUd, R_, RR, 0, nullptr, p_stds, TR, nullptr, R_, 0,
        T_, R_, R_, nullptr, nullptr, nullptr);
    // shared Cd + fused combine -> full d_out fp32
    bgemm<5,1><<<dim3(32,16,1),NTHR,GSMEM>>>(p_stds, R_, TR, 0,
        p_wsCd, R_, (size_t)H_*R_, 0, out, nullptr, 0, nullptr, H_, 0,
        T_, H_, R_, nullptr, nullptr, nullptr);
}

// round 13
// speedup vs baseline: 1.1559x; 1.1559x over previous
#include <cuda_runtime.h>
#include <cuda_bf16.h>
#include <math.h>
#include <stdint.h>

#define T_   4096
#define H_   2048
#define E_   32
#define KTOP 4
#define I_   1408
#define R_   128
#define SI_  2816
#define TK_  (T_*KTOP)

// ======================= scratch (device globals) =======================
__device__ __align__(16) int   g_cnt[E_];
__device__ __align__(16) int   g_off[E_+1];
__device__ __align__(16) int   g_tok2d[E_*T_];
__device__ __align__(16) float g_w2d[E_*T_];
__device__ __align__(16) int   g_tokslot[TK_];
__device__ __align__(16) float g_wslot[TK_];
__device__ __align__(16) int   g_slot_of[TK_];
__device__ __align__(16) int   g_tokc[T_];

// split bf16 hi/lo buffers (lo plane(s) after hi plane(s))
__device__ __align__(16) __nv_bfloat16 g_xs    [2u*T_*H_];
__device__ __align__(16) __nv_bfloat16 g_w_proj[2u*4*R_*H_];
__device__ __align__(16) __nv_bfloat16 g_w_Ug  [2u*E_*R_*R_];
__device__ __align__(16) __nv_bfloat16 g_w_Uu  [2u*E_*R_*R_];
__device__ __align__(16) __nv_bfloat16 g_w_Ud  [2u*E_*R_*R_];
__device__ __align__(16) __nv_bfloat16 g_w_Cg  [2u*E_*I_*R_];
__device__ __align__(16) __nv_bfloat16 g_w_Cu  [2u*E_*I_*R_];
__device__ __align__(16) __nv_bfloat16 g_w_Cd  [2u*E_*H_*R_];
__device__ __align__(16) __nv_bfloat16 g_w_Rd  [2u*R_*I_];
__device__ __align__(16) __nv_bfloat16 g_w_sU  [2u*2*R_*R_];
__device__ __align__(16) __nv_bfloat16 g_w_sCg [2u*SI_*R_];
__device__ __align__(16) __nv_bfloat16 g_w_sCu [2u*SI_*R_];
__device__ __align__(16) __nv_bfloat16 g_w_sRd [2u*R_*SI_];
__device__ __align__(16) __nv_bfloat16 g_w_sUd [2u*R_*R_];
__device__ __align__(16) __nv_bfloat16 g_w_sCd [2u*H_*R_];

__device__ __align__(16) __nv_bfloat16 g_proj_s[2u*4*T_*R_];
__device__ __align__(16) __nv_bfloat16 g_tg_s  [2u*TK_*R_];
__device__ __align__(16) __nv_bfloat16 g_tu_s  [2u*TK_*R_];
__device__ __align__(16) float         g_hf    [(size_t)TK_*I_];
__device__ __align__(16) __nv_bfloat16 g_h_s   [2u*(size_t)TK_*I_];
__device__ __align__(16) __nv_bfloat16 g_rd_s  [2u*TK_*R_];
__device__ __align__(16) __nv_bfloat16 g_td_s  [2u*TK_*R_];
__device__ __align__(16) __nv_bfloat16 g_st_s  [2u*2*T_*R_];
__device__ __align__(16) float         g_shf   [(size_t)T_*SI_];
__device__ __align__(16) __nv_bfloat16 g_sh_s  [2u*(size_t)T_*SI_];
__device__ __align__(16) float         g_skp   [8u*T_*R_];     // proj / expert-Rd partials (default stream)
__device__ __align__(16) float         g_skp2  [4u*T_*R_];     // shared-Rd partials (stream 2)
__device__ __align__(16) __nv_bfloat16 g_srd_s [2u*T_*R_];
__device__ __align__(16) __nv_bfloat16 g_std_s [2u*T_*R_];
__device__ __align__(16) float         g_eout  [(size_t)TK_*H_];

// ======================= helpers =======================
__device__ __forceinline__ uint32_t smem_u32_of(const void* p) {
    uint32_t a;
    asm("{ .reg .u64 t; cvta.to.shared.u64 t, %1; cvt.u32.u64 %0, t; }" : "=r"(a) : "l"(p));
    return a;
}
__device__ __forceinline__ void cpa16(uint32_t dst, const void* src, bool v) {
    int sz = v ? 16 : 0;
    asm volatile("cp.async.cg.shared.global [%0], [%1], 16, %2;\n" :: "r"(dst), "l"(src), "r"(sz));
}
__device__ __forceinline__ void ldm4(uint32_t* r, uint32_t addr) {
    asm volatile("ldmatrix.sync.aligned.m8n8.x4.shared.b16 {%0,%1,%2,%3}, [%4];"
                 : "=r"(r[0]), "=r"(r[1]), "=r"(r[2]), "=r"(r[3]) : "r"(addr));
}
__device__ __forceinline__ void mma_bf16(float* d, const uint32_t* a, const uint32_t* b) {
    asm volatile(
        "mma.sync.aligned.m16n8k16.row.col.f32.bf16.bf16.f32 "
        "{%0,%1,%2,%3},{%4,%5,%6,%7},{%8,%9},{%0,%1,%2,%3};\n"
        : "+f"(d[0]), "+f"(d[1]), "+f"(d[2]), "+f"(d[3])
        : "r"(a[0]), "r"(a[1]), "r"(a[2]), "r"(a[3]), "r"(b[0]), "r"(b[1]));
}
__device__ __forceinline__ float epi_silu(float v) { return v / (1.f + expf(-v)); }

// ======================= mega-split =======================
#define NJOBS 19
struct SplitJobs {
    const float*   src[NJOBS];
    __nv_bfloat16* dh [NJOBS];
    __nv_bfloat16* dl [NJOBS];
    unsigned       n  [NJOBS];
    unsigned       sb [NJOBS+1];
};

__global__ void megasplit_kernel(SplitJobs J) {
    unsigned bx = blockIdx.x;
    int j = 0;
    #pragma unroll
    for (int k = 0; k < NJOBS; k++) if (bx >= J.sb[k+1]) j = k+1;
    unsigned local = bx - J.sb[j];
    size_t i = ((size_t)local*256 + threadIdx.x) * 4;
    if (i >= J.n[j]) return;
    const float* src = J.src[j];
    __nv_bfloat16* dh = J.dh[j];
    __nv_bfloat16* dl = J.dl[j];
    float4 v = *reinterpret_cast<const float4*>(src + i);
    __nv_bfloat16 h0 = __float2bfloat16(v.x), h1 = __float2bfloat16(v.y);
    __nv_bfloat16 h2 = __float2bfloat16(v.z), h3 = __float2bfloat16(v.w);
    __nv_bfloat16 l0 = __float2bfloat16(v.x - __bfloat162float(h0));
    __nv_bfloat16 l1 = __float2bfloat16(v.y - __bfloat162float(h1));
    __nv_bfloat16 l2 = __float2bfloat16(v.z - __bfloat162float(h2));
    __nv_bfloat16 l3 = __float2bfloat16(v.w - __bfloat162float(h3));
    *reinterpret_cast<__nv_bfloat162*>(dh + i)     = __halves2bfloat162(h0, h1);
    *reinterpret_cast<__nv_bfloat162*>(dh + i + 2) = __halves2bfloat162(h2, h3);
    *reinterpret_cast<__nv_bfloat162*>(dl + i)     = __halves2bfloat162(l0, l1);
    *reinterpret_cast<__nv_bfloat162*>(dl + i + 2) = __halves2bfloat162(l2, l3);
}

// ======================= routing =======================
__global__ void init_kernel() {
    int i = blockIdx.x*256 + threadIdx.x;
    if (i < E_) g_cnt[i] = 0;
    if (i < T_) g_tokc[i] = 0;
}
__global__ void gate_kernel(const float* __restrict__ x, const float* __restrict__ gw) {
    __shared__ float xs[H_];
    __shared__ float lg[E_];
    int t = blockIdx.x;
    const float* xr = x + (size_t)t*H_;
    for (int i = threadIdx.x; i < H_; i += 256) xs[i] = xr[i];
    __syncthreads();
    int warp = threadIdx.x >> 5, lane = threadIdx.x & 31;
    for (int e = warp; e < E_; e += 8) {
        const float* w = gw + (size_t)e*H_;
        float s = 0.f;
        for (int i = lane; i < H_; i += 32) s += xs[i]*w[i];
        #pragma unroll
        for (int o = 16; o; o >>= 1) s += __shfl_xor_sync(0xffffffffu, s, o);
        if (lane == 0) lg[e] = s;
    }
    __syncthreads();
    if (threadIdx.x == 0) {
        float mx = lg[0];
        for (int e = 1; e < E_; e++) mx = fmaxf(mx, lg[e]);
        float p[E_]; float sum = 0.f;
        for (int e = 0; e < E_; e++) { p[e] = expf(lg[e]-mx); sum += p[e]; }
        float inv = 1.f/sum;
        bool taken[E_];
        for (int e = 0; e < E_; e++) taken[e] = false;
        int idx[KTOP]; float w4[KTOP]; float ws = 0.f;
        for (int k = 0; k < KTOP; k++) {
            int best = 0; float bv = -1.f;
            for (int e = 0; e < E_; e++)
                if (!taken[e] && p[e] > bv) { bv = p[e]; best = e; }
            taken[best] = true; idx[k] = best; w4[k] = bv*inv; ws += w4[k];
        }
        float rn = 1.f/(ws + 1e-20f);
        for (int k = 0; k < KTOP; k++) {
            int e = idx[k];
            int pos = atomicAdd(&g_cnt[e], 1);
            g_tok2d[e*T_ + pos] = t;
            g_w2d [e*T_ + pos] = w4[k]*rn;
        }
    }
}
__global__ void scan_kernel() {
    if (threadIdx.x == 0 && blockIdx.x == 0) {
        int a = 0;
        for (int e = 0; e < E_; e++) { g_off[e] = a; a += g_cnt[e]; }
        g_off[E_] = a;
    }
}
__global__ void compact_kernel() {
    int e = blockIdx.y;
    int i = blockIdx.x*256 + threadIdx.x;
    if (i < g_cnt[e]) {
        int slot = g_off[e] + i;
        int tok = g_tok2d[e*T_ + i];
        g_tokslot[slot] = tok;
        g_wslot[slot]   = g_w2d[e*T_ + i];
        int c = atomicAdd(&g_tokc[tok], 1);
        g_slot_of[tok*KTOP + c] = slot;
    }
}

// ======================= bf16-split mma.sync GEMM (round-10 proven config) =======================
// 128x128 CTA tile, 8 warps 32x64, 256 threads, 2 CTAs/SM, k-chunk 32, double-buffered.
// EPI: 0 split-store  1 silu->fp32  2 (res*Mul)->split-store  3 rowscale->fp32
//      4 fp32         5 fp32 + gather-add 4 expert slots
// ZMODE: 0 expert  1 dense-multi  2 split-K  3 dense-multi x split-K2 (z = plane*2+kh)

#define ROWW  20
#define TILEW (128*ROWW)
#define GSMEM (8*TILEW*4)

template<int EPI, int ZMODE>
__global__ __launch_bounds__(256, 2)
void bgemm(const __nv_bfloat16* __restrict__ Ah, int lda, size_t aplane, size_t astride,
           const __nv_bfloat16* __restrict__ Wh, int ldw, size_t wplane, size_t wstride,
           float* __restrict__ Cf,
           __nv_bfloat16* __restrict__ Ch, size_t cplane,
           const float* __restrict__ Mul,
           int ldc, size_t cstride,
           int M, int N, int Kd,
           const int* __restrict__ off,
           const int* __restrict__ rowmap,
           const float* __restrict__ rowscale)
{
    int z = blockIdx.z;
    int rs = 0, re = M;
    int kbase = 0;
    int zc = z;
    const __nv_bfloat16* A0 = Ah;
    const __nv_bfloat16* W0 = Wh;
    if (ZMODE == 0) { rs = off[z]; re = off[z+1]; W0 = Wh + (size_t)z*wstride; }
    else if (ZMODE == 1) { A0 = Ah + (size_t)z*astride; W0 = Wh + (size_t)z*wstride; }
    else if (ZMODE == 2) { kbase = z*Kd; }
    else {
        int zn = (int)(gridDim.z >> 1);
        int plane = z >> 1, kh = z & 1;
        A0 = Ah + (size_t)plane*astride;
        W0 = Wh + (size_t)plane*wstride;
        kbase = kh*Kd;
        zc = kh*zn + plane;
    }

    int row0 = rs + blockIdx.x * 128;
    if (row0 >= re) return;
    int col0 = blockIdx.y * 128;

    extern __shared__ uint32_t smw[];
    uint32_t sb = smem_u32_of(smw);

    int tid = threadIdx.x;
    int wid = tid >> 5, lane = tid & 31;
    int g = lane >> 2, t = lane & 3;
    int wm = wid & 3;
    int wn = wid >> 2;

    int aRow = ((lane >> 3) & 1)*8 + (lane & 7);
    int aCol = (lane >> 4)*4;
    int bRow = (lane >> 4)*8 + (lane & 7);
    int bCol = ((lane >> 3) & 1)*4;

    float acc[2][8][4];
    #pragma unroll
    for (int i = 0; i < 2; i++)
        #pragma unroll
        for (int j = 0; j < 8; j++)
            #pragma unroll
            for (int c = 0; c < 4; c++) acc[i][j][c] = 0.f;

    int iters = Kd / 32;

    auto stage = [&](int s, int kb) {
        uint32_t base = sb + (uint32_t)s*4*TILEW*4;
        #pragma unroll
        for (int it = 0; it < 8; it++) {
            int id = tid + it*256;
            int tile = id >> 9;
            int rem = id & 511;
            int row = rem >> 2;
            int seg = rem & 3;
            uint32_t dst = base + (uint32_t)(tile*TILEW + row*ROWW + seg*4)*4;
            int kpos = kbase + kb + seg*8;
            if (tile < 2) {
                int r = row0 + row;
                bool v = (r < re);
                int ar = 0;
                if (v) ar = (ZMODE == 0 && rowmap) ? rowmap[r] : r;
                const __nv_bfloat16* Ab = (tile == 0) ? A0 : (A0 + aplane);
                cpa16(dst, Ab + (size_t)ar*lda + kpos, v);
            } else {
                int n = col0 + row;
                const __nv_bfloat16* Wb = (tile == 2) ? W0 : (W0 + wplane);
                cpa16(dst, Wb + (size_t)n*ldw + kpos, true);
            }
        }
    };

    stage(0, 0);
    asm volatile("cp.async.commit_group;\n");

    for (int kt = 0; kt < iters; kt++) {
        if (kt + 1 < iters) {
            stage((kt+1) & 1, (kt+1)*32);
            asm volatile("cp.async.commit_group;\n");
            asm volatile("cp.async.wait_group 1;\n");
        } else {
            asm volatile("cp.async.wait_group 0;\n");
        }
        __syncthreads();
        uint32_t base = sb + (uint32_t)(kt & 1)*4*TILEW*4;

        #pragma unroll
        for (int kk = 0; kk < 16; kk += 8) {
            uint32_t aH[2][4], aL[2][4];
            #pragma unroll
            for (int mt = 0; mt < 2; mt++) {
                uint32_t ro = (uint32_t)((wm*32 + mt*16 + aRow)*ROWW + kk + aCol)*4;
                ldm4(aH[mt], base + 0*TILEW*4 + ro);
                ldm4(aL[mt], base + 1*TILEW*4 + ro);
            }
            #pragma unroll
            for (int half = 0; half < 2; half++) {
                uint32_t bH[2][4], bL[2][4];
                #pragma unroll
                for (int pp = 0; pp < 2; pp++) {
                    int p2 = half*2 + pp;
                    uint32_t ro = (uint32_t)((wn*64 + p2*16 + bRow)*ROWW + kk + bCol)*4;
                    ldm4(bH[pp], base + 2*TILEW*4 + ro);
                    ldm4(bL[pp], base + 3*TILEW*4 + ro);
                }
                #pragma unroll
                for (int mt = 0; mt < 2; mt++) {
                    #pragma unroll
                    for (int n4 = 0; n4 < 4; n4++) {
                        int nt = half*4 + n4;
                        int pp = n4 >> 1, w = (n4 & 1)*2;
                        mma_bf16(acc[mt][nt], aL[mt], &bH[pp][w]);
                        mma_bf16(acc[mt][nt], aH[mt], &bL[pp][w]);
                        mma_bf16(acc[mt][nt], aH[mt], &bH[pp][w]);
                    }
                }
            }
        }
        __syncthreads();
    }

    float* Cf_z = Cf;
    __nv_bfloat16* Ch_z = Ch;
    if (ZMODE == 1 || ZMODE == 2 || ZMODE == 3) {
        Cf_z = Cf + (size_t)zc*cstride;
        Ch_z = Ch + (size_t)zc*cstride;
    }
    #pragma unroll
    for (int mt = 0; mt < 2; mt++) {
        #pragma unroll
        for (int half = 0; half < 2; half++) {
            int r = row0 + wm*32 + mt*16 + g + half*8;
            if (r >= re) continue;
            float rsc = (EPI == 3) ? rowscale[r] : 1.f;
            int sl[KTOP];
            if (EPI == 5) {
                #pragma unroll
                for (int k = 0; k < KTOP; k++) sl[k] = g_slot_of[r*KTOP + k];
            }
            #pragma unroll
            for (int nt = 0; nt < 8; nt++) {
                int cix = col0 + wn*64 + nt*8 + 2*t;
                float v0 = acc[mt][nt][half*2 + 0];
                float v1 = acc[mt][nt][half*2 + 1];
                if (EPI == 1) { v0 = epi_silu(v0); v1 = epi_silu(v1); }
                if (EPI == 3) { v0 *= rsc; v1 *= rsc; }
                if (EPI == 2) {
                    float2 m = *reinterpret_cast<const float2*>(Mul + (size_t)r*ldc + cix);
                    v0 *= m.x; v1 *= m.y;
                }
                if (EPI == 5) {
                    #pragma unroll
                    for (int k = 0; k < KTOP; k++) {
                        float2 e2 = *reinterpret_cast<const float2*>(g_eout + (size_t)sl[k]*H_ + cix);
                        v0 += e2.x; v1 += e2.y;
                    }
                }
                if (EPI == 0 || EPI == 2) {
                    __nv_bfloat16 h0 = __float2bfloat16(v0);
                    __nv_bfloat16 h1 = __float2bfloat16(v1);
                    __nv_bfloat16 l0 = __float2bfloat16(v0 - __bfloat162float(h0));
                    __nv_bfloat16 l1 = __float2bfloat16(v1 - __bfloat162float(h1));
                    __nv_bfloat16* p = Ch_z + (size_t)r*ldc + cix;
                    *reinterpret_cast<__nv_bfloat162*>(p)          = __halves2bfloat162(h0, h1);
                    *reinterpret_cast<__nv_bfloat162*>(p + cplane) = __halves2bfloat162(l0, l1);
                } else {
                    float2 vv; vv.x = v0; vv.y = v1;
                    *reinterpret_cast<float2*>(Cf_z + (size_t)r*ldc + cix) = vv;
                }
            }
        }
    }
}

// ======================= N-plane split-K reduce -> split bf16 =======================
__global__ void reduceN_split_kernel(const float* __restrict__ in, size_t pstride, int np,
                                     __nv_bfloat16* __restrict__ dh, __nv_bfloat16* __restrict__ dl,
                                     int n) {
    int i = (blockIdx.x*256 + threadIdx.x) * 2;
    if (i >= n) return;
    float v0 = in[i], v1 = in[i+1];
    for (int p = 1; p < np; p++) {
        v0 += in[(size_t)p*pstride + i];
        v1 += in[(size_t)p*pstride + i + 1];
    }
    __nv_bfloat16 h0 = __float2bfloat16(v0), h1 = __float2bfloat16(v1);
    __nv_bfloat16 l0 = __float2bfloat16(v0 - __bfloat162float(h0));
    __nv_bfloat16 l1 = __float2bfloat16(v1 - __bfloat162float(h1));
    *reinterpret_cast<__nv_bfloat162*>(dh + i) = __halves2bfloat162(h0, h1);
    *reinterpret_cast<__nv_bfloat162*>(dl + i) = __halves2bfloat162(l0, l1);
}

// ======================= stream pack (static init, pre-baseline) =======================
struct StreamPack {
    cudaStream_t s2 = nullptr;
    cudaEvent_t ev0 = nullptr, ev1 = nullptr, ev2 = nullptr, ev3 = nullptr;
    bool ok = false;
    StreamPack() {
        ok = (cudaStreamCreateWithFlags(&s2, cudaStreamNonBlocking) == cudaSuccess)
          && (cudaEventCreateWithFlags(&ev0, cudaEventDisableTiming) == cudaSuccess)
          && (cudaEventCreateWithFlags(&ev1, cudaEventDisableTiming) == cudaSuccess)
          && (cudaEventCreateWithFlags(&ev2, cudaEventDisableTiming) == cudaSuccess)
          && (cudaEventCreateWithFlags(&ev3, cudaEventDisableTiming) == cudaSuccess);
    }
};
static StreamPack g_sp;

// ======================= host side =======================
template<typename Tp>
static Tp* sym(const void* s) {
    void* p = nullptr;
    cudaGetSymbolAddress(&p, s);
    return (Tp*)p;
}

extern "C" void kernel_launch(void* const* d_in, const int* in_sizes, int n_in,
                              void* d_out, int out_size)
{
    const float* x      = (const float*)d_in[0];
    const float* gate_w = (const float*)d_in[1];
    const float* Rg     = (const float*)d_in[2];
    const float* Ru     = (const float*)d_in[3];
    const float* Rd     = (const float*)d_in[4];
    const float* Ug     = (const float*)d_in[5];
    const float* Cg     = (const float*)d_in[6];
    const float* Uu     = (const float*)d_in[7];
    const float* Cu     = (const float*)d_in[8];
    const float* Ud     = (const float*)d_in[9];
    const float* Cd     = (const float*)d_in[10];
    const float* s_Rg   = (const float*)d_in[11];
    const float* s_Ug   = (const float*)d_in[12];
    const float* s_Cg   = (const float*)d_in[13];
    const float* s_Ru   = (const float*)d_in[14];
    const float* s_Uu   = (const float*)d_in[15];
    const float* s_Cu   = (const float*)d_in[16];
    const float* s_Rd   = (const float*)d_in[17];
    const float* s_Ud   = (const float*)d_in[18];
    const float* s_Cd   = (const float*)d_in[19];
    float* out = (float*)d_out;

    __nv_bfloat16* p_xs    = sym<__nv_bfloat16>(g_xs);
    __nv_bfloat16* p_wproj = sym<__nv_bfloat16>(g_w_proj);
    __nv_bfloat16* p_wUg   = sym<__nv_bfloat16>(g_w_Ug);
    __nv_bfloat16* p_wUu   = sym<__nv_bfloat16>(g_w_Uu);
    __nv_bfloat16* p_wUd   = sym<__nv_bfloat16>(g_w_Ud);
    __nv_bfloat16* p_wCg   = sym<__nv_bfloat16>(g_w_Cg);
    __nv_bfloat16* p_wCu   = sym<__nv_bfloat16>(g_w_Cu);
    __nv_bfloat16* p_wCd   = sym<__nv_bfloat16>(g_w_Cd);
    __nv_bfloat16* p_wRd   = sym<__nv_bfloat16>(g_w_Rd);
    __nv_bfloat16* p_wsU   = sym<__nv_bfloat16>(g_w_sU);
    __nv_bfloat16* p_wsCg  = sym<__nv_bfloat16>(g_w_sCg);
    __nv_bfloat16* p_wsCu  = sym<__nv_bfloat16>(g_w_sCu);
    __nv_bfloat16* p_wsRd  = sym<__nv_bfloat16>(g_w_sRd);
    __nv_bfloat16* p_wsUd  = sym<__nv_bfloat16>(g_w_sUd);
    __nv_bfloat16* p_wsCd  = sym<__nv_bfloat16>(g_w_sCd);

    __nv_bfloat16* p_projs = sym<__nv_bfloat16>(g_proj_s);
    __nv_bfloat16* p_tgs   = sym<__nv_bfloat16>(g_tg_s);
    __nv_bfloat16* p_tus   = sym<__nv_bfloat16>(g_tu_s);
    float*         p_hf    = sym<float>(g_hf);
    __nv_bfloat16* p_hs    = sym<__nv_bfloat16>(g_h_s);
    __nv_bfloat16* p_rds   = sym<__nv_bfloat16>(g_rd_s);
    __nv_bfloat16* p_tds   = sym<__nv_bfloat16>(g_td_s);
    __nv_bfloat16* p_sts   = sym<__nv_bfloat16>(g_st_s);
    float*         p_shf   = sym<float>(g_shf);
    __nv_bfloat16* p_shs   = sym<__nv_bfloat16>(g_sh_s);
    float*         p_skp   = sym<float>(g_skp);
    float*         p_skp2  = sym<float>(g_skp2);
    __nv_bfloat16* p_srds  = sym<__nv_bfloat16>(g_srd_s);
    __nv_bfloat16* p_stds  = sym<__nv_bfloat16>(g_std_s);
    float*         p_eout  = sym<float>(g_eout);
    int*   p_off = sym<int>(g_off);
    int*   p_map = sym<int>(g_tokslot);
    float* p_ws  = sym<float>(g_wslot);

    cudaFuncSetAttribute((const void*)bgemm<0,0>, cudaFuncAttributeMaxDynamicSharedMemorySize, GSMEM);
    cudaFuncSetAttribute((const void*)bgemm<0,1>, cudaFuncAttributeMaxDynamicSharedMemorySize, GSMEM);
    cudaFuncSetAttribute((const void*)bgemm<1,0>, cudaFuncAttributeMaxDynamicSharedMemorySize, GSMEM);
    cudaFuncSetAttribute((const void*)bgemm<1,1>, cudaFuncAttributeMaxDynamicSharedMemorySize, GSMEM);
    cudaFuncSetAttribute((const void*)bgemm<2,0>, cudaFuncAttributeMaxDynamicSharedMemorySize, GSMEM);
    cudaFuncSetAttribute((const void*)bgemm<2,1>, cudaFuncAttributeMaxDynamicSharedMemorySize, GSMEM);
    cudaFuncSetAttribute((const void*)bgemm<3,0>, cudaFuncAttributeMaxDynamicSharedMemorySize, GSMEM);
    cudaFuncSetAttribute((const void*)bgemm<4,2>, cudaFuncAttributeMaxDynamicSharedMemorySize, GSMEM);
    cudaFuncSetAttribute((const void*)bgemm<4,3>, cudaFuncAttributeMaxDynamicSharedMemorySize, GSMEM);
    cudaFuncSetAttribute((const void*)bgemm<5,1>, cudaFuncAttributeMaxDynamicSharedMemorySize, GSMEM);

    const size_t RH = (size_t)R_*H_, RR = (size_t)R_*R_;
    const size_t TR = (size_t)T_*R_, TKR = (size_t)TK_*R_, TKI = (size_t)TK_*I_, TSI = (size_t)T_*SI_;
    const size_t SIR = (size_t)SI_*R_;

    SplitJobs J;
    {
        const float* srcs[NJOBS] = { x, Rg, Ru, s_Rg, s_Ru, Ug, Uu, Ud, Cg, Cu, Cd, Rd,
                                     s_Ug, s_Uu, s_Cg, s_Cu, s_Rd, s_Ud, s_Cd };
        __nv_bfloat16* dhs[NJOBS] = {
            p_xs, p_wproj + 0*RH, p_wproj + 1*RH, p_wproj + 2*RH, p_wproj + 3*RH,
            p_wUg, p_wUu, p_wUd, p_wCg, p_wCu, p_wCd, p_wRd,
            p_wsU + 0*RR, p_wsU + 1*RR, p_wsCg, p_wsCu, p_wsRd, p_wsUd, p_wsCd };
        __nv_bfloat16* dls[NJOBS] = {
            p_xs + (size_t)T_*H_, p_wproj + 4*RH + 0*RH, p_wproj + 4*RH + 1*RH,
            p_wproj + 4*RH + 2*RH, p_wproj + 4*RH + 3*RH,
            p_wUg + (size_t)E_*RR, p_wUu + (size_t)E_*RR, p_wUd + (size_t)E_*RR,
            p_wCg + (size_t)E_*I_*R_, p_wCu + (size_t)E_*I_*R_, p_wCd + (size_t)E_*H_*R_,
            p_wRd + (size_t)R_*I_,
            p_wsU + 2*RR + 0*RR, p_wsU + 2*RR + 1*RR,
            p_wsCg + SIR, p_wsCu + SIR, p_wsRd + (size_t)R_*SI_,
            p_wsUd + RR, p_wsCd + (size_t)H_*R_ };
        size_t ns[NJOBS] = { (size_t)T_*H_, RH, RH, RH, RH,
                             (size_t)E_*RR, (size_t)E_*RR, (size_t)E_*RR,
                             (size_t)E_*I_*R_, (size_t)E_*I_*R_, (size_t)E_*H_*R_,
                             (size_t)R_*I_, RR, RR, SIR, SIR, (size_t)R_*SI_, RR, (size_t)H_*R_ };
        unsigned acc = 0;
        for (int j = 0; j < NJOBS; j++) {
            J.src[j] = srcs[j]; J.dh[j] = dhs[j]; J.dl[j] = dls[j];
            J.n[j] = (unsigned)ns[j];
            J.sb[j] = acc;
            acc += (unsigned)((ns[j] + 1023) / 1024);
        }
        J.sb[NJOBS] = acc;
    }

    const bool par = g_sp.ok;
    cudaStream_t s2 = par ? g_sp.s2 : (cudaStream_t)0;

    // Fork root: event on the captured (default) stream so s2's work is rooted in the graph.
    if (par) { cudaEventRecord(g_sp.ev0, 0); cudaStreamWaitEvent(s2, g_sp.ev0, 0); }

    // ---- branch B (s2): routing — depends only on x ----
    init_kernel<<<16,256,0,s2>>>();
    gate_kernel<<<T_,256,0,s2>>>(x, gate_w);
    scan_kernel<<<1,32,0,s2>>>();
    compact_kernel<<<dim3(16,E_),256,0,s2>>>();
    if (par) cudaEventRecord(g_sp.ev1, s2);

    // ---- branch A (default): splits + proj ----
    megasplit_kernel<<<J.sb[NJOBS],256>>>(J);
    bgemm<4,3><<<dim3(32,1,8),256,GSMEM>>>(p_xs, H_, (size_t)T_*H_, 0,
        p_wproj, H_, 4*RH, RH, p_skp, nullptr, 0, nullptr, R_, TR,
        T_, R_, H_/2, nullptr, nullptr, nullptr);
    reduceN_split_kernel<<<(4*T_*R_/2+255)/256,256>>>(p_skp, 4*TR, 2, p_projs, p_projs + 4*TR, 4*T_*R_);
    if (par) cudaEventRecord(g_sp.ev2, 0);

    // ---- branch B (s2): shared-expert chain — needs proj planes (ev2); weights staged before proj on default ----
    if (par) cudaStreamWaitEvent(s2, g_sp.ev2, 0);
    bgemm<0,1><<<dim3(32,1,2),256,GSMEM,s2>>>(p_projs + 2*TR, R_, 4*TR, TR,
        p_wsU, R_, 2*RR, RR, nullptr, p_sts, 2*TR, nullptr, R_, TR,
        T_, R_, R_, nullptr, nullptr, nullptr);
    bgemm<1,1><<<dim3(32,22,1),256,GSMEM,s2>>>(p_sts + 0*TR, R_, 2*TR, 0,
        p_wsCg, R_, SIR, 0, p_shf, nullptr, 0, nullptr, SI_, 0,
        T_, SI_, R_, nullptr, nullptr, nullptr);
    bgemm<2,1><<<dim3(32,22,1),256,GSMEM,s2>>>(p_sts + 1*TR, R_, 2*TR, 0,
        p_wsCu, R_, SIR, 0, nullptr, p_shs, TSI, p_shf, SI_, 0,
        T_, SI_, R_, nullptr, nullptr, nullptr);
    bgemm<4,2><<<dim3(32,1,4),256,GSMEM,s2>>>(p_shs, SI_, TSI, 0,
        p_wsRd, SI_, (size_t)R_*SI_, 0, p_skp2, nullptr, 0, nullptr, R_, TR,
        T_, R_, SI_/4, nullptr, nullptr, nullptr);
    reduceN_split_kernel<<<(T_*R_/2+255)/256,256,0,s2>>>(p_skp2, TR, 4, p_srds, p_srds + TR, T_*R_);
    bgemm<0,1><<<dim3(32,1,1),256,GSMEM,s2>>>(p_srds, R_, TR, 0,
        p_wsUd, R_, RR, 0, nullptr, p_stds, TR, nullptr, R_, 0,
        T_, R_, R_, nullptr, nullptr, nullptr);
    if (par) cudaEventRecord(g_sp.ev3, s2);

    // ---- branch A (default): expert chain — needs routing (ev1) + proj planes (same stream) ----
    if (par) cudaStreamWaitEvent((cudaStream_t)0, g_sp.ev1, 0);
    bgemm<0,0><<<dim3(32,1,E_),256,GSMEM>>>(p_projs + 0*TR, R_, 4*TR, 0,
        p_wUg, R_, (size_t)E_*RR, RR, nullptr, p_tgs, TKR, nullptr, R_, 0,
        0, R_, R_, p_off, p_map, nullptr);
    bgemm<0,0><<<dim3(32,1,E_),256,GSMEM>>>(p_projs + 1*TR, R_, 4*TR, 0,
        p_wUu, R_, (size_t)E_*RR, RR, nullptr, p_tus, TKR, nullptr, R_, 0,
        0, R_, R_, p_off, p_map, nullptr);
    bgemm<1,0><<<dim3(32,11,E_),256,GSMEM>>>(p_tgs, R_, TKR, 0,
        p_wCg, R_, (size_t)E_*I_*R_, (size_t)I_*R_, p_hf, nullptr, 0, nullptr, I_, 0,
        0, I_, R_, p_off, nullptr, nullptr);
    bgemm<2,0><<<dim3(32,11,E_),256,GSMEM>>>(p_tus, R_, TKR, 0,
        p_wCu, R_, (size_t)E_*I_*R_, (size_t)I_*R_, nullptr, p_hs, TKI, p_hf, I_, 0,
        0, I_, R_, p_off, nullptr, nullptr);
    bgemm<4,2><<<dim3(128,1,2),256,GSMEM>>>(p_hs, I_, TKI, 0,
        p_wRd, I_, (size_t)R_*I_, 0, p_skp, nullptr, 0, nullptr, R_, TKR,
        TK_, R_, I_/2, nullptr, nullptr, nullptr);
    reduceN_split_kernel<<<(TK_*R_/2+255)/256,256>>>(p_skp, TKR, 2, p_rds, p_rds + TKR, TK_*R_);
    bgemm<0,0><<<dim3(32,1,E_),256,GSMEM>>>(p_rds, R_, TKR, 0,
        p_wUd, R_, (size_t)E_*RR, RR, nullptr, p_tds, TKR, nullptr, R_, 0,
        0, R_, R_, p_off, nullptr, nullptr);
    bgemm<3,0><<<dim3(32,16,E_),256,GSMEM>>>(p_tds, R_, TKR, 0,
        p_wCd, R_, (size_t)E_*H_*R_, (size_t)H_*R_, p_eout, nullptr, 0, nullptr, H_, 0,
        0, H_, R_, p_off, nullptr, p_ws);

    // ---- join: final shared-Cd + fused combine needs both branches ----
    if (par) cudaStreamWaitEvent((cudaStream_t)0, g_sp.ev3, 0);
    bgemm<5,1><<<dim3(32,16,1),256,GSMEM>>>(p_stds, R_, TR, 0,
        p_wsCd, R_, (size_t)H_*R_, 0, out, nullptr, 0, nullptr, H_, 0,
        T_, H_, R_, nullptr, nullptr, nullptr);
}

// round 14
// speedup vs baseline: 1.2305x; 1.0646x over previous
#include <cuda_runtime.h>
#include <cuda_bf16.h>
#include <math.h>
#include <stdint.h>

#define T_   4096
#define H_   2048
#define E_   32
#define KTOP 4
#define I_   1408
#define R_   128
#define SI_  2816
#define TK_  (T_*KTOP)

// ======================= scratch (device globals) =======================
__device__ __align__(16) int   g_cnt[E_];
__device__ __align__(16) int   g_off[E_+1];
__device__ __align__(16) int   g_tok2d[E_*T_];
__device__ __align__(16) float g_w2d[E_*T_];
__device__ __align__(16) int   g_tokslot[TK_];
__device__ __align__(16) float g_wslot[TK_];
__device__ __align__(16) int   g_slot_of[TK_];
__device__ __align__(16) int   g_tokc[T_];

__device__ __align__(16) __nv_bfloat16 g_xs    [2u*T_*H_];
__device__ __align__(16) __nv_bfloat16 g_w_proj[2u*4*R_*H_];
__device__ __align__(16) __nv_bfloat16 g_w_Ug  [2u*E_*R_*R_];
__device__ __align__(16) __nv_bfloat16 g_w_Uu  [2u*E_*R_*R_];
__device__ __align__(16) __nv_bfloat16 g_w_Ud  [2u*E_*R_*R_];
__device__ __align__(16) __nv_bfloat16 g_w_Cg  [2u*E_*I_*R_];
__device__ __align__(16) __nv_bfloat16 g_w_Cu  [2u*E_*I_*R_];
__device__ __align__(16) __nv_bfloat16 g_w_Cd  [2u*E_*H_*R_];
__device__ __align__(16) __nv_bfloat16 g_w_Rd  [2u*R_*I_];
__device__ __align__(16) __nv_bfloat16 g_w_sU  [2u*2*R_*R_];
__device__ __align__(16) __nv_bfloat16 g_w_sCg [2u*SI_*R_];
__device__ __align__(16) __nv_bfloat16 g_w_sCu [2u*SI_*R_];
__device__ __align__(16) __nv_bfloat16 g_w_sRd [2u*R_*SI_];
__device__ __align__(16) __nv_bfloat16 g_w_sUd [2u*R_*R_];
__device__ __align__(16) __nv_bfloat16 g_w_sCd [2u*H_*R_];

__device__ __align__(16) __nv_bfloat16 g_proj_s[2u*4*T_*R_];
__device__ __align__(16) __nv_bfloat16 g_tg_s  [2u*TK_*R_];
__device__ __align__(16) __nv_bfloat16 g_tu_s  [2u*TK_*R_];
__device__ __align__(16) float         g_hf    [(size_t)TK_*I_];
__device__ __align__(16) __nv_bfloat16 g_h_s   [2u*(size_t)TK_*I_];
__device__ __align__(16) __nv_bfloat16 g_rd_s  [2u*TK_*R_];
__device__ __align__(16) __nv_bfloat16 g_td_s  [2u*TK_*R_];
__device__ __align__(16) __nv_bfloat16 g_st_s  [2u*2*T_*R_];
__device__ __align__(16) float         g_shf   [(size_t)T_*SI_];
__device__ __align__(16) __nv_bfloat16 g_sh_s  [2u*(size_t)T_*SI_];
__device__ __align__(16) float         g_skp   [8u*T_*R_];     // proj / expert-Rd partials (stream A)
__device__ __align__(16) float         g_skp2  [4u*T_*R_];     // shared-Rd partials (stream 2)
__device__ __align__(16) __nv_bfloat16 g_srd_s [2u*T_*R_];
__device__ __align__(16) __nv_bfloat16 g_std_s [2u*T_*R_];
__device__ __align__(16) float         g_eout  [(size_t)TK_*H_];

// ======================= helpers =======================
__device__ __forceinline__ uint32_t smem_u32_of(const void* p) {
    uint32_t a;
    asm("{ .reg .u64 t; cvta.to.shared.u64 t, %1; cvt.u32.u64 %0, t; }" : "=r"(a) : "l"(p));
    return a;
}
__device__ __forceinline__ void cpa16(uint32_t dst, const void* src, bool v) {
    int sz = v ? 16 : 0;
    asm volatile("cp.async.cg.shared.global [%0], [%1], 16, %2;\n" :: "r"(dst), "l"(src), "r"(sz));
}
__device__ __forceinline__ void ldm4(uint32_t* r, uint32_t addr) {
    asm volatile("ldmatrix.sync.aligned.m8n8.x4.shared.b16 {%0,%1,%2,%3}, [%4];"
                 : "=r"(r[0]), "=r"(r[1]), "=r"(r[2]), "=r"(r[3]) : "r"(addr));
}
__device__ __forceinline__ void mma_bf16(float* d, const uint32_t* a, const uint32_t* b) {
    asm volatile(
        "mma.sync.aligned.m16n8k16.row.col.f32.bf16.bf16.f32 "
        "{%0,%1,%2,%3},{%4,%5,%6,%7},{%8,%9},{%0,%1,%2,%3};\n"
        : "+f"(d[0]), "+f"(d[1]), "+f"(d[2]), "+f"(d[3])
        : "r"(a[0]), "r"(a[1]), "r"(a[2]), "r"(a[3]), "r"(b[0]), "r"(b[1]));
}
__device__ __forceinline__ float epi_silu(float v) { return v / (1.f + expf(-v)); }

// ======================= split kernel (job table, padded) =======================
#define NJOBS 19
struct SplitJobs {
    const float*   src[NJOBS];
    __nv_bfloat16* dh [NJOBS];
    __nv_bfloat16* dl [NJOBS];
    unsigned       n  [NJOBS];
    unsigned       sb [NJOBS+1];
};

__global__ void megasplit_kernel(SplitJobs J) {
    unsigned bx = blockIdx.x;
    int j = 0;
    #pragma unroll
    for (int k = 0; k < NJOBS; k++) if (bx >= J.sb[k+1]) j = k+1;
    unsigned local = bx - J.sb[j];
    size_t i = ((size_t)local*256 + threadIdx.x) * 4;
    if (i >= J.n[j]) return;
    const float* src = J.src[j];
    __nv_bfloat16* dh = J.dh[j];
    __nv_bfloat16* dl = J.dl[j];
    float4 v = *reinterpret_cast<const float4*>(src + i);
    __nv_bfloat16 h0 = __float2bfloat16(v.x), h1 = __float2bfloat16(v.y);
    __nv_bfloat16 h2 = __float2bfloat16(v.z), h3 = __float2bfloat16(v.w);
    __nv_bfloat16 l0 = __float2bfloat16(v.x - __bfloat162float(h0));
    __nv_bfloat16 l1 = __float2bfloat16(v.y - __bfloat162float(h1));
    __nv_bfloat16 l2 = __float2bfloat16(v.z - __bfloat162float(h2));
    __nv_bfloat16 l3 = __float2bfloat16(v.w - __bfloat162float(h3));
    *reinterpret_cast<__nv_bfloat162*>(dh + i)     = __halves2bfloat162(h0, h1);
    *reinterpret_cast<__nv_bfloat162*>(dh + i + 2) = __halves2bfloat162(h2, h3);
    *reinterpret_cast<__nv_bfloat162*>(dl + i)     = __halves2bfloat162(l0, l1);
    *reinterpret_cast<__nv_bfloat162*>(dl + i + 2) = __halves2bfloat162(l2, l3);
}

// ======================= routing =======================
__global__ void init_kernel() {
    int i = blockIdx.x*256 + threadIdx.x;
    if (i < E_) g_cnt[i] = 0;
    if (i < T_) g_tokc[i] = 0;
}
__global__ void gate_kernel(const float* __restrict__ x, const float* __restrict__ gw) {
    __shared__ float xs[H_];
    __shared__ float lg[E_];
    int t = blockIdx.x;
    const float* xr = x + (size_t)t*H_;
    for (int i = threadIdx.x; i < H_; i += 256) xs[i] = xr[i];
    __syncthreads();
    int warp = threadIdx.x >> 5, lane = threadIdx.x & 31;
    for (int e = warp; e < E_; e += 8) {
        const float* w = gw + (size_t)e*H_;
        float s = 0.f;
        for (int i = lane; i < H_; i += 32) s += xs[i]*w[i];
        #pragma unroll
        for (int o = 16; o; o >>= 1) s += __shfl_xor_sync(0xffffffffu, s, o);
        if (lane == 0) lg[e] = s;
    }
    __syncthreads();
    if (threadIdx.x == 0) {
        float mx = lg[0];
        for (int e = 1; e < E_; e++) mx = fmaxf(mx, lg[e]);
        float p[E_]; float sum = 0.f;
        for (int e = 0; e < E_; e++) { p[e] = expf(lg[e]-mx); sum += p[e]; }
        float inv = 1.f/sum;
        bool taken[E_];
        for (int e = 0; e < E_; e++) taken[e] = false;
        int idx[KTOP]; float w4[KTOP]; float ws = 0.f;
        for (int k = 0; k < KTOP; k++) {
            int best = 0; float bv = -1.f;
            for (int e = 0; e < E_; e++)
                if (!taken[e] && p[e] > bv) { bv = p[e]; best = e; }
            taken[best] = true; idx[k] = best; w4[k] = bv*inv; ws += w4[k];
        }
        float rn = 1.f/(ws + 1e-20f);
        for (int k = 0; k < KTOP; k++) {
            int e = idx[k];
            int pos = atomicAdd(&g_cnt[e], 1);
            g_tok2d[e*T_ + pos] = t;
            g_w2d [e*T_ + pos] = w4[k]*rn;
        }
    }
}
__global__ void scan_kernel() {
    if (threadIdx.x == 0 && blockIdx.x == 0) {
        int a = 0;
        for (int e = 0; e < E_; e++) { g_off[e] = a; a += g_cnt[e]; }
        g_off[E_] = a;
    }
}
__global__ void compact_kernel() {
    int e = blockIdx.y;
    int i = blockIdx.x*256 + threadIdx.x;
    if (i < g_cnt[e]) {
        int slot = g_off[e] + i;
        int tok = g_tok2d[e*T_ + i];
        g_tokslot[slot] = tok;
        g_wslot[slot]   = g_w2d[e*T_ + i];
        int c = atomicAdd(&g_tokc[tok], 1);
        g_slot_of[tok*KTOP + c] = slot;
    }
}

// ======================= bf16-split mma.sync GEMM (proven config) =======================
#define ROWW  20
#define TILEW (128*ROWW)
#define GSMEM (8*TILEW*4)

template<int EPI, int ZMODE>
__global__ __launch_bounds__(256, 2)
void bgemm(const __nv_bfloat16* __restrict__ Ah, int lda, size_t aplane, size_t astride,
           const __nv_bfloat16* __restrict__ Wh, int ldw, size_t wplane, size_t wstride,
           float* __restrict__ Cf,
           __nv_bfloat16* __restrict__ Ch, size_t cplane,
           const float* __restrict__ Mul,
           int ldc, size_t cstride,
           int M, int N, int Kd,
           const int* __restrict__ off,
           const int* __restrict__ rowmap,
           const float* __restrict__ rowscale)
{
    int z = blockIdx.z;
    int rs = 0, re = M;
    int kbase = 0;
    int zc = z;
    const __nv_bfloat16* A0 = Ah;
    const __nv_bfloat16* W0 = Wh;
    if (ZMODE == 0) { rs = off[z]; re = off[z+1]; W0 = Wh + (size_t)z*wstride; }
    else if (ZMODE == 1) { A0 = Ah + (size_t)z*astride; W0 = Wh + (size_t)z*wstride; }
    else if (ZMODE == 2) { kbase = z*Kd; }
    else {
        int zn = (int)(gridDim.z >> 1);
        int plane = z >> 1, kh = z & 1;
        A0 = Ah + (size_t)plane*astride;
        W0 = Wh + (size_t)plane*wstride;
        kbase = kh*Kd;
        zc = kh*zn + plane;
    }

    int row0 = rs + blockIdx.x * 128;
    if (row0 >= re) return;
    int col0 = blockIdx.y * 128;

    extern __shared__ uint32_t smw[];
    uint32_t sb = smem_u32_of(smw);

    int tid = threadIdx.x;
    int wid = tid >> 5, lane = tid & 31;
    int g = lane >> 2, t = lane & 3;
    int wm = wid & 3;
    int wn = wid >> 2;

    int aRow = ((lane >> 3) & 1)*8 + (lane & 7);
    int aCol = (lane >> 4)*4;
    int bRow = (lane >> 4)*8 + (lane & 7);
    int bCol = ((lane >> 3) & 1)*4;

    float acc[2][8][4];
    #pragma unroll
    for (int i = 0; i < 2; i++)
        #pragma unroll
        for (int j = 0; j < 8; j++)
            #pragma unroll
            for (int c = 0; c < 4; c++) acc[i][j][c] = 0.f;

    int iters = Kd / 32;

    auto stage = [&](int s, int kb) {
        uint32_t base = sb + (uint32_t)s*4*TILEW*4;
        #pragma unroll
        for (int it = 0; it < 8; it++) {
            int id = tid + it*256;
            int tile = id >> 9;
            int rem = id & 511;
            int row = rem >> 2;
            int seg = rem & 3;
            uint32_t dst = base + (uint32_t)(tile*TILEW + row*ROWW + seg*4)*4;
            int kpos = kbase + kb + seg*8;
            if (tile < 2) {
                int r = row0 + row;
                bool v = (r < re);
                int ar = 0;
                if (v) ar = (ZMODE == 0 && rowmap) ? rowmap[r] : r;
                const __nv_bfloat16* Ab = (tile == 0) ? A0 : (A0 + aplane);
                cpa16(dst, Ab + (size_t)ar*lda + kpos, v);
            } else {
                int n = col0 + row;
                const __nv_bfloat16* Wb = (tile == 2) ? W0 : (W0 + wplane);
                cpa16(dst, Wb + (size_t)n*ldw + kpos, true);
            }
        }
    };

    stage(0, 0);
    asm volatile("cp.async.commit_group;\n");

    for (int kt = 0; kt < iters; kt++) {
        if (kt + 1 < iters) {
            stage((kt+1) & 1, (kt+1)*32);
            asm volatile("cp.async.commit_group;\n");
            asm volatile("cp.async.wait_group 1;\n");
        } else {
            asm volatile("cp.async.wait_group 0;\n");
        }
        __syncthreads();
        uint32_t base = sb + (uint32_t)(kt & 1)*4*TILEW*4;

        #pragma unroll
        for (int kk = 0; kk < 16; kk += 8) {
            uint32_t aH[2][4], aL[2][4];
            #pragma unroll
            for (int mt = 0; mt < 2; mt++) {
                uint32_t ro = (uint32_t)((wm*32 + mt*16 + aRow)*ROWW + kk + aCol)*4;
                ldm4(aH[mt], base + 0*TILEW*4 + ro);
                ldm4(aL[mt], base + 1*TILEW*4 + ro);
            }
            #pragma unroll
            for (int half = 0; half < 2; half++) {
                uint32_t bH[2][4], bL[2][4];
                #pragma unroll
                for (int pp = 0; pp < 2; pp++) {
                    int p2 = half*2 + pp;
                    uint32_t ro = (uint32_t)((wn*64 + p2*16 + bRow)*ROWW + kk + bCol)*4;
                    ldm4(bH[pp], base + 2*TILEW*4 + ro);
                    ldm4(bL[pp], base + 3*TILEW*4 + ro);
                }
                #pragma unroll
                for (int mt = 0; mt < 2; mt++) {
                    #pragma unroll
                    for (int n4 = 0; n4 < 4; n4++) {
                        int nt = half*4 + n4;
                        int pp = n4 >> 1, w = (n4 & 1)*2;
                        mma_bf16(acc[mt][nt], aL[mt], &bH[pp][w]);
                        mma_bf16(acc[mt][nt], aH[mt], &bL[pp][w]);
                        mma_bf16(acc[mt][nt], aH[mt], &bH[pp][w]);
                    }
                }
            }
        }
        __syncthreads();
    }

    float* Cf_z = Cf;
    __nv_bfloat16* Ch_z = Ch;
    if (ZMODE == 1 || ZMODE == 2 || ZMODE == 3) {
        Cf_z = Cf + (size_t)zc*cstride;
        Ch_z = Ch + (size_t)zc*cstride;
    }
    #pragma unroll
    for (int mt = 0; mt < 2; mt++) {
        #pragma unroll
        for (int half = 0; half < 2; half++) {
            int r = row0 + wm*32 + mt*16 + g + half*8;
            if (r >= re) continue;
            float rsc = (EPI == 3) ? rowscale[r] : 1.f;
            int sl[KTOP];
            if (EPI == 5) {
                #pragma unroll
                for (int k = 0; k < KTOP; k++) sl[k] = g_slot_of[r*KTOP + k];
            }
            #pragma unroll
            for (int nt = 0; nt < 8; nt++) {
                int cix = col0 + wn*64 + nt*8 + 2*t;
                float v0 = acc[mt][nt][half*2 + 0];
                float v1 = acc[mt][nt][half*2 + 1];
                if (EPI == 1) { v0 = epi_silu(v0); v1 = epi_silu(v1); }
                if (EPI == 3) { v0 *= rsc; v1 *= rsc; }
                if (EPI == 2) {
                    float2 m = *reinterpret_cast<const float2*>(Mul + (size_t)r*ldc + cix);
                    v0 *= m.x; v1 *= m.y;
                }
                if (EPI == 5) {
                    #pragma unroll
                    for (int k = 0; k < KTOP; k++) {
                        float2 e2 = *reinterpret_cast<const float2*>(g_eout + (size_t)sl[k]*H_ + cix);
                        v0 += e2.x; v1 += e2.y;
                    }
                }
                if (EPI == 0 || EPI == 2) {
                    __nv_bfloat16 h0 = __float2bfloat16(v0);
                    __nv_bfloat16 h1 = __float2bfloat16(v1);
                    __nv_bfloat16 l0 = __float2bfloat16(v0 - __bfloat162float(h0));
                    __nv_bfloat16 l1 = __float2bfloat16(v1 - __bfloat162float(h1));
                    __nv_bfloat16* p = Ch_z + (size_t)r*ldc + cix;
                    *reinterpret_cast<__nv_bfloat162*>(p)          = __halves2bfloat162(h0, h1);
                    *reinterpret_cast<__nv_bfloat162*>(p + cplane) = __halves2bfloat162(l0, l1);
                } else {
                    float2 vv; vv.x = v0; vv.y = v1;
                    *reinterpret_cast<float2*>(Cf_z + (size_t)r*ldc + cix) = vv;
                }
            }
        }
    }
}

// ======================= N-plane split-K reduce -> split bf16 =======================
__global__ void reduceN_split_kernel(const float* __restrict__ in, size_t pstride, int np,
                                     __nv_bfloat16* __restrict__ dh, __nv_bfloat16* __restrict__ dl,
                                     int n) {
    int i = (blockIdx.x*256 + threadIdx.x) * 2;
    if (i >= n) return;
    float v0 = in[i], v1 = in[i+1];
    for (int p = 1; p < np; p++) {
        v0 += in[(size_t)p*pstride + i];
        v1 += in[(size_t)p*pstride + i + 1];
    }
    __nv_bfloat16 h0 = __float2bfloat16(v0), h1 = __float2bfloat16(v1);
    __nv_bfloat16 l0 = __float2bfloat16(v0 - __bfloat162float(h0));
    __nv_bfloat16 l1 = __float2bfloat16(v1 - __bfloat162float(h1));
    *reinterpret_cast<__nv_bfloat162*>(dh + i) = __halves2bfloat162(h0, h1);
    *reinterpret_cast<__nv_bfloat162*>(dl + i) = __halves2bfloat162(l0, l1);
}

// ======================= stream pack (static init, pre-baseline) =======================
struct StreamPack {
    cudaStream_t s2 = nullptr;
    cudaEvent_t ev0 = nullptr, ev1 = nullptr, evB = nullptr, ev2 = nullptr, ev_uu = nullptr, ev3 = nullptr;
    bool ok = false;
    StreamPack() {
        ok = (cudaStreamCreateWithFlags(&s2, cudaStreamNonBlocking) == cudaSuccess)
          && (cudaEventCreateWithFlags(&ev0,  cudaEventDisableTiming) == cudaSuccess)
          && (cudaEventCreateWithFlags(&ev1,  cudaEventDisableTiming) == cudaSuccess)
          && (cudaEventCreateWithFlags(&evB,  cudaEventDisableTiming) == cudaSuccess)
          && (cudaEventCreateWithFlags(&ev2,  cudaEventDisableTiming) == cudaSuccess)
          && (cudaEventCreateWithFlags(&ev_uu,cudaEventDisableTiming) == cudaSuccess)
          && (cudaEventCreateWithFlags(&ev3,  cudaEventDisableTiming) == cudaSuccess);
    }
};
static StreamPack g_sp;

// ======================= host side =======================
template<typename Tp>
static Tp* sym(const void* s) {
    void* p = nullptr;
    cudaGetSymbolAddress(&p, s);
    return (Tp*)p;
}

static void build_jobs(SplitJobs& J, int cnt,
                       const float* const* srcs, __nv_bfloat16* const* dhs,
                       __nv_bfloat16* const* dls, const size_t* ns)
{
    unsigned acc = 0;
    for (int j = 0; j < cnt; j++) {
        J.src[j] = srcs[j]; J.dh[j] = dhs[j]; J.dl[j] = dls[j];
        J.n[j] = (unsigned)ns[j];
        J.sb[j] = acc;
        acc += (unsigned)((ns[j] + 1023) / 1024);
    }
    for (int j = cnt; j < NJOBS; j++) {
        J.src[j] = nullptr; J.dh[j] = nullptr; J.dl[j] = nullptr;
        J.n[j] = 0; J.sb[j] = acc;
    }
    J.sb[NJOBS] = acc;
}

extern "C" void kernel_launch(void* const* d_in, const int* in_sizes, int n_in,
                              void* d_out, int out_size)
{
    const float* x      = (const float*)d_in[0];
    const float* gate_w = (const float*)d_in[1];
    const float* Rg     = (const float*)d_in[2];
    const float* Ru     = (const float*)d_in[3];
    const float* Rd     = (const float*)d_in[4];
    const float* Ug     = (const float*)d_in[5];
    const float* Cg     = (const float*)d_in[6];
    const float* Uu     = (const float*)d_in[7];
    const float* Cu     = (const float*)d_in[8];
    const float* Ud     = (const float*)d_in[9];
    const float* Cd     = (const float*)d_in[10];
    const float* s_Rg   = (const float*)d_in[11];
    const float* s_Ug   = (const float*)d_in[12];
    const float* s_Cg   = (const float*)d_in[13];
    const float* s_Ru   = (const float*)d_in[14];
    const float* s_Uu   = (const float*)d_in[15];
    const float* s_Cu   = (const float*)d_in[16];
    const float* s_Rd   = (const float*)d_in[17];
    const float* s_Ud   = (const float*)d_in[18];
    const float* s_Cd   = (const float*)d_in[19];
    float* out = (float*)d_out;

    __nv_bfloat16* p_xs    = sym<__nv_bfloat16>(g_xs);
    __nv_bfloat16* p_wproj = sym<__nv_bfloat16>(g_w_proj);
    __nv_bfloat16* p_wUg   = sym<__nv_bfloat16>(g_w_Ug);
    __nv_bfloat16* p_wUu   = sym<__nv_bfloat16>(g_w_Uu);
    __nv_bfloat16* p_wUd   = sym<__nv_bfloat16>(g_w_Ud);
    __nv_bfloat16* p_wCg   = sym<__nv_bfloat16>(g_w_Cg);
    __nv_bfloat16* p_wCu   = sym<__nv_bfloat16>(g_w_Cu);
    __nv_bfloat16* p_wCd   = sym<__nv_bfloat16>(g_w_Cd);
    __nv_bfloat16* p_wRd   = sym<__nv_bfloat16>(g_w_Rd);
    __nv_bfloat16* p_wsU   = sym<__nv_bfloat16>(g_w_sU);
    __nv_bfloat16* p_wsCg  = sym<__nv_bfloat16>(g_w_sCg);
    __nv_bfloat16* p_wsCu  = sym<__nv_bfloat16>(g_w_sCu);
    __nv_bfloat16* p_wsRd  = sym<__nv_bfloat16>(g_w_sRd);
    __nv_bfloat16* p_wsUd  = sym<__nv_bfloat16>(g_w_sUd);
    __nv_bfloat16* p_wsCd  = sym<__nv_bfloat16>(g_w_sCd);

    __nv_bfloat16* p_projs = sym<__nv_bfloat16>(g_proj_s);
    __nv_bfloat16* p_tgs   = sym<__nv_bfloat16>(g_tg_s);
    __nv_bfloat16* p_tus   = sym<__nv_bfloat16>(g_tu_s);
    float*         p_hf    = sym<float>(g_hf);
    __nv_bfloat16* p_hs    = sym<__nv_bfloat16>(g_h_s);
    __nv_bfloat16* p_rds   = sym<__nv_bfloat16>(g_rd_s);
    __nv_bfloat16* p_tds   = sym<__nv_bfloat16>(g_td_s);
    __nv_bfloat16* p_sts   = sym<__nv_bfloat16>(g_st_s);
    float*         p_shf   = sym<float>(g_shf);
    __nv_bfloat16* p_shs   = sym<__nv_bfloat16>(g_sh_s);
    float*         p_skp   = sym<float>(g_skp);
    float*         p_skp2  = sym<float>(g_skp2);
    __nv_bfloat16* p_srds  = sym<__nv_bfloat16>(g_srd_s);
    __nv_bfloat16* p_stds  = sym<__nv_bfloat16>(g_std_s);
    float*         p_eout  = sym<float>(g_eout);
    int*   p_off = sym<int>(g_off);
    int*   p_map = sym<int>(g_tokslot);
    float* p_ws  = sym<float>(g_wslot);

    cudaFuncSetAttribute((const void*)bgemm<0,0>, cudaFuncAttributeMaxDynamicSharedMemorySize, GSMEM);
    cudaFuncSetAttribute((const void*)bgemm<0,1>, cudaFuncAttributeMaxDynamicSharedMemorySize, GSMEM);
    cudaFuncSetAttribute((const void*)bgemm<1,0>, cudaFuncAttributeMaxDynamicSharedMemorySize, GSMEM);
    cudaFuncSetAttribute((const void*)bgemm<1,1>, cudaFuncAttributeMaxDynamicSharedMemorySize, GSMEM);
    cudaFuncSetAttribute((const void*)bgemm<2,0>, cudaFuncAttributeMaxDynamicSharedMemorySize, GSMEM);
    cudaFuncSetAttribute((const void*)bgemm<2,1>, cudaFuncAttributeMaxDynamicSharedMemorySize, GSMEM);
    cudaFuncSetAttribute((const void*)bgemm<3,0>, cudaFuncAttributeMaxDynamicSharedMemorySize, GSMEM);
    cudaFuncSetAttribute((const void*)bgemm<4,2>, cudaFuncAttributeMaxDynamicSharedMemorySize, GSMEM);
    cudaFuncSetAttribute((const void*)bgemm<4,3>, cudaFuncAttributeMaxDynamicSharedMemorySize, GSMEM);
    cudaFuncSetAttribute((const void*)bgemm<5,1>, cudaFuncAttributeMaxDynamicSharedMemorySize, GSMEM);

    const size_t RH = (size_t)R_*H_, RR = (size_t)R_*R_;
    const size_t TR = (size_t)T_*R_, TKR = (size_t)TK_*R_, TKI = (size_t)TK_*I_, TSI = (size_t)T_*SI_;
    const size_t SIR = (size_t)SI_*R_;

    // ---- split job tables ----
    SplitJobs JA, JB;
    {
        // splitA: x + projection weights (feeds proj GEMM)
        const float* srcsA[5] = { x, Rg, Ru, s_Rg, s_Ru };
        __nv_bfloat16* dhsA[5] = { p_xs, p_wproj + 0*RH, p_wproj + 1*RH, p_wproj + 2*RH, p_wproj + 3*RH };
        __nv_bfloat16* dlsA[5] = { p_xs + (size_t)T_*H_, p_wproj + 4*RH + 0*RH, p_wproj + 4*RH + 1*RH,
                                   p_wproj + 4*RH + 2*RH, p_wproj + 4*RH + 3*RH };
        size_t nsA[5] = { (size_t)T_*H_, RH, RH, RH, RH };
        build_jobs(JA, 5, srcsA, dhsA, dlsA, nsA);

        // splitB: everything else (feeds expert + shared chains)
        const float* srcsB[14] = { Ug, Uu, Ud, Cg, Cu, Cd, Rd, s_Ug, s_Uu, s_Cg, s_Cu, s_Rd, s_Ud, s_Cd };
        __nv_bfloat16* dhsB[14] = { p_wUg, p_wUu, p_wUd, p_wCg, p_wCu, p_wCd, p_wRd,
                                    p_wsU + 0*RR, p_wsU + 1*RR, p_wsCg, p_wsCu, p_wsRd, p_wsUd, p_wsCd };
        __nv_bfloat16* dlsB[14] = { p_wUg + (size_t)E_*RR, p_wUu + (size_t)E_*RR, p_wUd + (size_t)E_*RR,
                                    p_wCg + (size_t)E_*I_*R_, p_wCu + (size_t)E_*I_*R_, p_wCd + (size_t)E_*H_*R_,
                                    p_wRd + (size_t)R_*I_,
                                    p_wsU + 2*RR + 0*RR, p_wsU + 2*RR + 1*RR,
                                    p_wsCg + SIR, p_wsCu + SIR, p_wsRd + (size_t)R_*SI_,
                                    p_wsUd + RR, p_wsCd + (size_t)H_*R_ };
        size_t nsB[14] = { (size_t)E_*RR, (size_t)E_*RR, (size_t)E_*RR,
                           (size_t)E_*I_*R_, (size_t)E_*I_*R_, (size_t)E_*H_*R_, (size_t)R_*I_,
                           RR, RR, SIR, SIR, (size_t)R_*SI_, RR, (size_t)H_*R_ };
        build_jobs(JB, 14, srcsB, dhsB, dlsB, nsB);
    }

    const bool par = g_sp.ok;
    cudaStream_t s2 = par ? g_sp.s2 : (cudaStream_t)0;

    // Fork root on captured stream.
    if (par) { cudaEventRecord(g_sp.ev0, 0); cudaStreamWaitEvent(s2, g_sp.ev0, 0); }

    // ---- s2: routing (needs only x) ----
    init_kernel<<<16,256,0,s2>>>();
    gate_kernel<<<T_,256,0,s2>>>(x, gate_w);
    scan_kernel<<<1,32,0,s2>>>();
    compact_kernel<<<dim3(16,E_),256,0,s2>>>();
    if (par) cudaEventRecord(g_sp.ev1, s2);

    // ---- s2: splitB (expert/shared weights) ----
    megasplit_kernel<<<JB.sb[NJOBS],256,0,s2>>>(JB);
    if (par) cudaEventRecord(g_sp.evB, s2);

    // ---- A: splitA + proj ----
    megasplit_kernel<<<JA.sb[NJOBS],256>>>(JA);
    bgemm<4,3><<<dim3(32,1,8),256,GSMEM>>>(p_xs, H_, (size_t)T_*H_, 0,
        p_wproj, H_, 4*RH, RH, p_skp, nullptr, 0, nullptr, R_, TR,
        T_, R_, H_/2, nullptr, nullptr, nullptr);
    reduceN_split_kernel<<<(4*T_*R_/2+255)/256,256>>>(p_skp, 4*TR, 2, p_projs, p_projs + 4*TR, 4*T_*R_);
    if (par) cudaEventRecord(g_sp.ev2, 0);

    // ---- s2: expert U-up (needs routing[s2], splitB[s2], proj[ev2]) ----
    if (par) cudaStreamWaitEvent(s2, g_sp.ev2, 0);
    bgemm<0,0><<<dim3(32,1,E_),256,GSMEM,s2>>>(p_projs + 1*TR, R_, 4*TR, 0,
        p_wUu, R_, (size_t)E_*RR, RR, nullptr, p_tus, TKR, nullptr, R_, 0,
        0, R_, R_, p_off, p_map, nullptr);
    if (par) cudaEventRecord(g_sp.ev_uu, s2);

    // ---- s2: shared-expert chain ----
    bgemm<0,1><<<dim3(32,1,2),256,GSMEM,s2>>>(p_projs + 2*TR, R_, 4*TR, TR,
        p_wsU, R_, 2*RR, RR, nullptr, p_sts, 2*TR, nullptr, R_, TR,
        T_, R_, R_, nullptr, nullptr, nullptr);
    bgemm<1,1><<<dim3(32,22,1),256,GSMEM,s2>>>(p_sts + 0*TR, R_, 2*TR, 0,
        p_wsCg, R_, SIR, 0, p_shf, nullptr, 0, nullptr, SI_, 0,
        T_, SI_, R_, nullptr, nullptr, nullptr);
    bgemm<2,1><<<dim3(32,22,1),256,GSMEM,s2>>>(p_sts + 1*TR, R_, 2*TR, 0,
        p_wsCu, R_, SIR, 0, nullptr, p_shs, TSI, p_shf, SI_, 0,
        T_, SI_, R_, nullptr, nullptr, nullptr);
    bgemm<4,2><<<dim3(32,1,4),256,GSMEM,s2>>>(p_shs, SI_, TSI, 0,
        p_wsRd, SI_, (size_t)R_*SI_, 0, p_skp2, nullptr, 0, nullptr, R_, TR,
        T_, R_, SI_/4, nullptr, nullptr, nullptr);
    reduceN_split_kernel<<<(T_*R_/2+255)/256,256,0,s2>>>(p_skp2, TR, 4, p_srds, p_srds + TR, T_*R_);
    bgemm<0,1><<<dim3(32,1,1),256,GSMEM,s2>>>(p_srds, R_, TR, 0,
        p_wsUd, R_, RR, 0, nullptr, p_stds, TR, nullptr, R_, 0,
        T_, R_, R_, nullptr, nullptr, nullptr);
    if (par) cudaEventRecord(g_sp.ev3, s2);

    // ---- A: expert chain (needs routing ev1 + splitB evB; proj on same stream) ----
    if (par) {
        cudaStreamWaitEvent((cudaStream_t)0, g_sp.ev1, 0);
        cudaStreamWaitEvent((cudaStream_t)0, g_sp.evB, 0);
    }
    bgemm<0,0><<<dim3(32,1,E_),256,GSMEM>>>(p_projs + 0*TR, R_, 4*TR, 0,
        p_wUg, R_, (size_t)E_*RR, RR, nullptr, p_tgs, TKR, nullptr, R_, 0,
        0, R_, R_, p_off, p_map, nullptr);
    bgemm<1,0><<<dim3(32,11,E_),256,GSMEM>>>(p_tgs, R_, TKR, 0,
        p_wCg, R_, (size_t)E_*I_*R_, (size_t)I_*R_, p_hf, nullptr, 0, nullptr, I_, 0,
        0, I_, R_, p_off, nullptr, nullptr);
    // Cu needs tu from s2 (ev_uu) and hf from Cg (same stream)
    if (par) cudaStreamWaitEvent((cudaStream_t)0, g_sp.ev_uu, 0);
    bgemm<2,0><<<dim3(32,11,E_),256,GSMEM>>>(p_tus, R_, TKR, 0,
        p_wCu, R_, (size_t)E_*I_*R_, (size_t)I_*R_, nullptr, p_hs, TKI, p_hf, I_, 0,
        0, I_, R_, p_off, nullptr, nullptr);
    bgemm<4,2><<<dim3(128,1,2),256,GSMEM>>>(p_hs, I_, TKI, 0,
        p_wRd, I_, (size_t)R_*I_, 0, p_skp, nullptr, 0, nullptr, R_, TKR,
        TK_, R_, I_/2, nullptr, nullptr, nullptr);
    reduceN_split_kernel<<<(TK_*R_/2+255)/256,256>>>(p_skp, TKR, 2, p_rds, p_rds + TKR, TK_*R_);
    bgemm<0,0><<<dim3(32,1,E_),256,GSMEM>>>(p_rds, R_, TKR, 0,
        p_wUd, R_, (size_t)E_*RR, RR, nullptr, p_tds, TKR, nullptr, R_, 0,
        0, R_, R_, p_off, nullptr, nullptr);
    bgemm<3,0><<<dim3(32,16,E_),256,GSMEM>>>(p_tds, R_, TKR, 0,
        p_wCd, R_, (size_t)E_*H_*R_, (size_t)H_*R_, p_eout, nullptr, 0, nullptr, H_, 0,
        0, H_, R_, p_off, nullptr, p_ws);

    // ---- join: final shared-Cd + fused combine ----
    if (par) cudaStreamWaitEvent((cudaStream_t)0, g_sp.ev3, 0);
    bgemm<5,1><<<dim3(32,16,1),256,GSMEM>>>(p_stds, R_, TR, 0,
        p_wsCd, R_, (size_t)H_*R_, 0, out, nullptr, 0, nullptr, H_, 0,
        T_, H_, R_, nullptr, nullptr, nullptr);
}